// round 1
// baseline (speedup 1.0000x reference)
#include <cuda_runtime.h>
#include <math.h>

#define B_  2
#define E_  1024
#define DM_ 512
#define H_  8
#define DK_ 64
#define DV_ 64
#define MAXN 5

// d_out layout: x_out [B,DM,E] | attn [B,H,E,E] | attn_per_edge [B,E]
constexpr long OFF_ATTN = (long)B_ * DM_ * E_;                 // 1,048,576
constexpr long OFF_APE  = OFF_ATTN + (long)B_ * H_ * E_ * E_;  // +16,777,216

// ---------------- scratch (device globals; no allocation allowed) -------------
__device__ float g_s [B_*E_*DM_];      // s[b*E+e][d]
__device__ float g_qn[B_*E_*DM_];      // layer-normed s
__device__ float g_q [B_*H_*E_*DK_];   // qs = q / sqrt(DK), per-head layout
__device__ float g_k [B_*H_*E_*DK_];
__device__ float g_v [B_*H_*E_*DV_];
__device__ float g_qr[B_*H_*E_*8];     // qr[row][c], c in 0..5 (stride 8)
__device__ float g_o [B_*E_*H_*DV_];   // attn@V in [b,e, h*DV+d] layout
__device__ float g_num[B_*E_];
__device__ float g_den[B_*E_];

// ---------------- 1) transpose x[b][d][e] -> s[b][e][d] ----------------------
__global__ void k_transpose(const float* __restrict__ x) {
    __shared__ float tile[32][33];
    int b  = blockIdx.z;
    int e0 = blockIdx.x * 32, d0 = blockIdx.y * 32;
    int tx = threadIdx.x, ty = threadIdx.y;
#pragma unroll
    for (int l = 0; l < 4; l++) {
        int d = d0 + ty + l * 8;
        tile[ty + l * 8][tx] = x[((long)b * DM_ + d) * E_ + e0 + tx];
    }
    __syncthreads();
#pragma unroll
    for (int l = 0; l < 4; l++) {
        int e = e0 + ty + l * 8;
        g_s[((long)b * E_ + e) * DM_ + d0 + tx] = tile[tx][ty + l * 8];
    }
}

// ---------------- 2) LayerNorm rows of s -> qn --------------------------------
__global__ void k_ln(const float* __restrict__ gamma, const float* __restrict__ beta) {
    int r = blockIdx.x, t = threadIdx.x;           // 128 threads
    const float* sp = g_s + (long)r * DM_;
    float v[4];
#pragma unroll
    for (int k = 0; k < 4; k++) v[k] = sp[t + 128 * k];

    __shared__ float red[128];
    float s = v[0] + v[1] + v[2] + v[3];
    red[t] = s; __syncthreads();
    for (int o = 64; o > 0; o >>= 1) { if (t < o) red[t] += red[t + o]; __syncthreads(); }
    float mean = red[0] * (1.0f / DM_);
    __syncthreads();

    float sq = 0.f;
#pragma unroll
    for (int k = 0; k < 4; k++) { float d = v[k] - mean; sq += d * d; }
    red[t] = sq; __syncthreads();
    for (int o = 64; o > 0; o >>= 1) { if (t < o) red[t] += red[t + o]; __syncthreads(); }
    float var = red[0] * (1.0f / DM_);
    float inv = 1.0f / sqrtf(var + 1e-6f);

#pragma unroll
    for (int k = 0; k < 4; k++) {
        int d = t + 128 * k;
        g_qn[(long)r * DM_ + d] = (v[k] - mean) * inv * gamma[d] + beta[d];
    }
}

// ---------------- 3) tiled GEMM, 64x64 tile, 4x4/thread -----------------------
// MODE 0: q = qn @ w_q * 1/8 -> g_q (head layout)
// MODE 1: k = s  @ w_k       -> g_k
// MODE 2: v = s  @ w_v       -> g_v
// MODE 3: y = o  @ w_fc + s  -> d_out x_out region (transposed scatter)
template<int MODE>
__global__ void k_gemm(const float* __restrict__ W, float* __restrict__ out) {
    __shared__ float As[32][65];
    __shared__ float Ws[32][64];
    const float* A = (MODE == 0) ? g_qn : ((MODE == 3) ? g_o : g_s);

    int m0 = blockIdx.y * 64, n0 = blockIdx.x * 64;
    int tx = threadIdx.x, ty = threadIdx.y;
    int tid = ty * 16 + tx;
    float acc[4][4] = {};

    for (int k0 = 0; k0 < DM_; k0 += 32) {
#pragma unroll
        for (int l = 0; l < 8; l++) {
            int idx = tid + l * 256;
            int kk = idx & 31, mm = idx >> 5;
            As[kk][mm] = A[(long)(m0 + mm) * DM_ + k0 + kk];
        }
#pragma unroll
        for (int l = 0; l < 8; l++) {
            int idx = tid + l * 256;
            int nn = idx & 63, kk = idx >> 6;
            Ws[kk][nn] = W[(long)(k0 + kk) * 512 + n0 + nn];
        }
        __syncthreads();
#pragma unroll
        for (int k = 0; k < 32; k++) {
            float a[4], w[4];
#pragma unroll
            for (int i = 0; i < 4; i++) a[i] = As[k][ty + 16 * i];
#pragma unroll
            for (int j = 0; j < 4; j++) w[j] = Ws[k][tx + 16 * j];
#pragma unroll
            for (int i = 0; i < 4; i++)
#pragma unroll
                for (int j = 0; j < 4; j++) acc[i][j] += a[i] * w[j];
        }
        __syncthreads();
    }

#pragma unroll
    for (int i = 0; i < 4; i++)
#pragma unroll
        for (int j = 0; j < 4; j++) {
            int m = m0 + ty + 16 * i, n = n0 + tx + 16 * j;
            float val = acc[i][j];
            if (MODE == 0) val *= 0.125f;                 // 1/sqrt(DK)
            if (MODE <= 2) {
                int b = m >> 10, e = m & 1023;
                int h = n >> 6,  d = n & 63;
                float* o = (MODE == 0) ? g_q : (MODE == 1) ? g_k : g_v;
                o[(((long)(b * H_ + h)) * E_ + e) * 64 + d] = val;
            } else {
                int b = m >> 10, e = m & 1023;
                val += g_s[(long)m * DM_ + n];            // residual
                out[((long)b * DM_ + n) * E_ + e] = val;  // x_out[b][d][e]
            }
        }
}

// ---------------- 4) qr[row][c] = qs_row . base_rpr[c] ------------------------
__global__ void k_qr(const float* __restrict__ rpr) {
    int row = blockIdx.x;
    int d = threadIdx.x;                       // 64 threads
    int lane = d & 31, w = d >> 5;
    float qv = g_q[(long)row * 64 + d];
    __shared__ float sh[2];
#pragma unroll
    for (int c = 0; c < 6; c++) {
        float p = qv * rpr[c * 64 + d];
#pragma unroll
        for (int o = 16; o; o >>= 1) p += __shfl_down_sync(0xffffffffu, p, o);
        if (lane == 0) sh[w] = p;
        __syncthreads();
        if (d == 0) g_qr[(long)row * 8 + c] = sh[0] + sh[1];
        __syncthreads();
    }
}

// ---------------- 5) logits = qs@k^T + qr[dist] (masked) ----------------------
__global__ void k_logits(const int* __restrict__ dist, float* __restrict__ attn) {
    __shared__ float Qs[64][65];
    __shared__ float Ks[64][65];
    __shared__ float Qr[64][8];
    int bh = blockIdx.z;
    int b  = bh >> 3;
    int i0 = blockIdx.y * 64, j0 = blockIdx.x * 64;
    int tx = threadIdx.x, ty = threadIdx.y;
    int tid = ty * 16 + tx;

    const float* qp = g_q + (long)bh * E_ * 64;
    const float* kp = g_k + (long)bh * E_ * 64;
#pragma unroll
    for (int l = 0; l < 16; l++) {
        int idx = tid + l * 256;
        int dd = idx & 63, r = idx >> 6;
        Qs[r][dd] = qp[(long)(i0 + r) * 64 + dd];
        Ks[r][dd] = kp[(long)(j0 + r) * 64 + dd];
    }
#pragma unroll
    for (int l = 0; l < 2; l++) {
        int idx = tid + l * 256;
        int c = idx & 7, r = idx >> 3;
        Qr[r][c] = g_qr[((long)bh * E_ + i0 + r) * 8 + c];
    }
    __syncthreads();

    float acc[4][4] = {};
#pragma unroll
    for (int d = 0; d < 64; d++) {
        float a[4], w[4];
#pragma unroll
        for (int i = 0; i < 4; i++) a[i] = Qs[ty + 16 * i][d];
#pragma unroll
        for (int j = 0; j < 4; j++) w[j] = Ks[tx + 16 * j][d];
#pragma unroll
        for (int i = 0; i < 4; i++)
#pragma unroll
            for (int j = 0; j < 4; j++) acc[i][j] += a[i] * w[j];
    }

#pragma unroll
    for (int ii = 0; ii < 4; ii++)
#pragma unroll
        for (int jj = 0; jj < 4; jj++) {
            int i = i0 + ty + 16 * ii, j = j0 + tx + 16 * jj;
            int c = dist[((long)b * E_ + i) * E_ + j];
            float v = (c <= MAXN) ? acc[ii][jj] + Qr[ty + 16 * ii][c] : -1e9f;
            attn[((long)bh * E_ + i) * E_ + j] = v;
        }
}

// ---------------- 6) row softmax in place -------------------------------------
__global__ void k_softmax(float* __restrict__ attn) {
    long row = blockIdx.x;
    float* p = attn + row * 1024;
    int t = threadIdx.x;                       // 256 threads
    float v[4];
#pragma unroll
    for (int k = 0; k < 4; k++) v[k] = p[t + 256 * k];

    __shared__ float red[256];
    float m = fmaxf(fmaxf(v[0], v[1]), fmaxf(v[2], v[3]));
    red[t] = m; __syncthreads();
    for (int o = 128; o > 0; o >>= 1) { if (t < o) red[t] = fmaxf(red[t], red[t + o]); __syncthreads(); }
    m = red[0];
    __syncthreads();

    float e[4], s = 0.f;
#pragma unroll
    for (int k = 0; k < 4; k++) { e[k] = expf(v[k] - m); s += e[k]; }
    red[t] = s; __syncthreads();
    for (int o = 128; o > 0; o >>= 1) { if (t < o) red[t] += red[t + o]; __syncthreads(); }
    float inv = 1.0f / red[0];
#pragma unroll
    for (int k = 0; k < 4; k++) p[t + 256 * k] = e[k] * inv;
}

// ---------------- 7) out = attn @ v  -> g_o[b,e,h*64+d] -----------------------
__global__ void k_av(const float* __restrict__ attn) {
    __shared__ float As[32][65];               // As[j][i]
    __shared__ float Vs[32][64];               // Vs[j][d]
    int bh = blockIdx.y;
    int b = bh >> 3, h = bh & 7;
    int i0 = blockIdx.x * 64;
    int tx = threadIdx.x, ty = threadIdx.y;
    int tid = ty * 16 + tx;

    const float* ap = attn + (long)bh * E_ * E_;
    const float* vp = g_v + (long)bh * E_ * 64;
    float acc[4][4] = {};

    for (int j0 = 0; j0 < E_; j0 += 32) {
#pragma unroll
        for (int l = 0; l < 8; l++) {
            int idx = tid + l * 256;
            int jc = idx & 31, r = idx >> 5;
            As[jc][r] = ap[(long)(i0 + r) * E_ + j0 + jc];
        }
#pragma unroll
        for (int l = 0; l < 8; l++) {
            int idx = tid + l * 256;
            int dd = idx & 63, jr = idx >> 6;
            Vs[jr][dd] = vp[(long)(j0 + jr) * 64 + dd];
        }
        __syncthreads();
#pragma unroll
        for (int k = 0; k < 32; k++) {
            float a[4], w[4];
#pragma unroll
            for (int i = 0; i < 4; i++) a[i] = As[k][ty + 16 * i];
#pragma unroll
            for (int j = 0; j < 4; j++) w[j] = Vs[k][tx + 16 * j];
#pragma unroll
            for (int i = 0; i < 4; i++)
#pragma unroll
                for (int j = 0; j < 4; j++) acc[i][j] += a[i] * w[j];
        }
        __syncthreads();
    }

#pragma unroll
    for (int ii = 0; ii < 4; ii++)
#pragma unroll
        for (int jj = 0; jj < 4; jj++) {
            int i = i0 + ty + 16 * ii;
            int dd = tx + 16 * jj;
            g_o[((long)(b * E_ + i)) * 512 + h * 64 + dd] = acc[ii][jj];
        }
}

// ---------------- 8) attn_per_edge --------------------------------------------
__global__ void k_zero() {
    int i = blockIdx.x * 256 + threadIdx.x;
    if (i < B_ * E_) { g_num[i] = 0.f; g_den[i] = 0.f; }
}

__global__ void k_ape_num(const float* __restrict__ attn) {
    int b = blockIdx.y;
    int row0 = blockIdx.x * 128;               // row = h*E + i in [0, 8192)
    int t = threadIdx.x;                       // 256 threads
    float s[4] = {};
    const float* base = attn + ((long)b * (H_ * E_) + row0) * 1024;
    for (int rr = 0; rr < 128; rr++) {
        const float* p = base + (long)rr * 1024;
#pragma unroll
        for (int k = 0; k < 4; k++) s[k] += p[t + 256 * k];
    }
#pragma unroll
    for (int k = 0; k < 4; k++) atomicAdd(&g_num[b * 1024 + t + 256 * k], s[k]);
}

__global__ void k_ape_den(const int* __restrict__ dist) {
    int b = blockIdx.y;
    int i0 = blockIdx.x * 128;
    int t = threadIdx.x;
    int cnt[4] = {};
    for (int rr = 0; rr < 128; rr++) {
        const int* p = dist + ((long)b * E_ + i0 + rr) * E_;
#pragma unroll
        for (int k = 0; k < 4; k++) cnt[k] += (p[t + 256 * k] <= MAXN) ? 1 : 0;
    }
#pragma unroll
    for (int k = 0; k < 4; k++) atomicAdd(&g_den[b * 1024 + t + 256 * k], (float)cnt[k]);
}

__global__ void k_ape_fin(float* __restrict__ out) {
    int i = blockIdx.x * 256 + threadIdx.x;
    if (i < B_ * E_) out[i] = g_num[i] / g_den[i];
}

// ---------------- launcher ----------------------------------------------------
extern "C" void kernel_launch(void* const* d_in, const int* in_sizes, int n_in,
                              void* d_out, int out_size) {
    const float* x       = (const float*)d_in[0];
    const int*   dist    = (const int*)  d_in[1];
    const float* rpr     = (const float*)d_in[2];
    const float* w_q     = (const float*)d_in[3];
    const float* w_k     = (const float*)d_in[4];
    const float* w_v     = (const float*)d_in[5];
    const float* w_fc    = (const float*)d_in[6];
    const float* ln_g    = (const float*)d_in[7];
    const float* ln_b    = (const float*)d_in[8];

    float* out   = (float*)d_out;
    float* attn  = out + OFF_ATTN;
    float* ape   = out + OFF_APE;

    dim3 b16(16, 16);

    k_zero<<<8, 256>>>();
    k_transpose<<<dim3(E_ / 32, DM_ / 32, B_), dim3(32, 8)>>>(x);
    k_ln<<<B_ * E_, 128>>>(ln_g, ln_b);

    k_gemm<0><<<dim3(8, 32), b16>>>(w_q, nullptr);
    k_gemm<1><<<dim3(8, 32), b16>>>(w_k, nullptr);
    k_gemm<2><<<dim3(8, 32), b16>>>(w_v, nullptr);

    k_qr<<<B_ * H_ * E_, 64>>>(rpr);

    k_logits<<<dim3(E_ / 64, E_ / 64, B_ * H_), b16>>>(dist, attn);
    k_softmax<<<B_ * H_ * E_, 256>>>(attn);

    k_av<<<dim3(E_ / 64, B_ * H_), b16>>>(attn);
    k_gemm<3><<<dim3(8, 32), b16>>>(w_fc, out);

    k_ape_num<<<dim3(64, B_), 256>>>(attn);
    k_ape_den<<<dim3(8, B_), 256>>>(dist);
    k_ape_fin<<<8, 256>>>(ape);
}

// round 2
// speedup vs baseline: 1.5110x; 1.5110x over previous
#include <cuda_runtime.h>
#include <cstdint>
#include <math.h>

#define B_  2
#define E_  1024
#define DM_ 512
#define H_  8
#define DK_ 64
#define DV_ 64
#define MAXN 5

// d_out layout: x_out [B,DM,E] | attn [B,H,E,E] | attn_per_edge [B,E]
constexpr long OFF_ATTN = (long)B_ * DM_ * E_;
constexpr long OFF_APE  = OFF_ATTN + (long)B_ * H_ * E_ * E_;

// ---------------- scratch ------------------------------------------------------
__device__ float g_s [B_*E_*DM_];
__device__ float g_qn[B_*E_*DM_];
__device__ float g_q [B_*H_*E_*DK_];
__device__ float g_k [B_*H_*E_*DK_];
__device__ float g_v [B_*H_*E_*DV_];
__device__ float g_qr[B_*H_*E_*8];
__device__ float g_o [B_*E_*H_*DV_];
__device__ float g_num[B_*E_];
__device__ float g_den[B_*E_];

// ---------------- helpers ------------------------------------------------------
__device__ __forceinline__ float tf32r(float x) {
    asm("cvt.rna.tf32.f32 %0, %0;" : "+f"(x));
    return x;
}
__device__ __forceinline__ uint32_t f2u(float x) { return __float_as_uint(x); }

__device__ __forceinline__ void mma_tf32(float c[4], const uint32_t a[4], const uint32_t b[2]) {
    asm volatile(
        "mma.sync.aligned.m16n8k8.row.col.f32.tf32.tf32.f32 "
        "{%0,%1,%2,%3}, {%4,%5,%6,%7}, {%8,%9}, {%0,%1,%2,%3};"
        : "+f"(c[0]), "+f"(c[1]), "+f"(c[2]), "+f"(c[3])
        : "r"(a[0]), "r"(a[1]), "r"(a[2]), "r"(a[3]), "r"(b[0]), "r"(b[1]));
}

// ---------------- 1) transpose x[b][d][e] -> s[b][e][d] ------------------------
__global__ void k_transpose(const float* __restrict__ x) {
    __shared__ float tile[32][33];
    int b  = blockIdx.z;
    int e0 = blockIdx.x * 32, d0 = blockIdx.y * 32;
    int tx = threadIdx.x, ty = threadIdx.y;
#pragma unroll
    for (int l = 0; l < 4; l++) {
        int d = d0 + ty + l * 8;
        tile[ty + l * 8][tx] = x[((long)b * DM_ + d) * E_ + e0 + tx];
    }
    __syncthreads();
#pragma unroll
    for (int l = 0; l < 4; l++) {
        int e = e0 + ty + l * 8;
        g_s[((long)b * E_ + e) * DM_ + d0 + tx] = tile[tx][ty + l * 8];
    }
}

// ---------------- 2) LayerNorm -------------------------------------------------
__global__ void k_ln(const float* __restrict__ gamma, const float* __restrict__ beta) {
    int r = blockIdx.x, t = threadIdx.x;           // 128 threads
    const float* sp = g_s + (long)r * DM_;
    float v[4];
#pragma unroll
    for (int k = 0; k < 4; k++) v[k] = sp[t + 128 * k];

    __shared__ float red[128];
    float s = v[0] + v[1] + v[2] + v[3];
    red[t] = s; __syncthreads();
    for (int o = 64; o > 0; o >>= 1) { if (t < o) red[t] += red[t + o]; __syncthreads(); }
    float mean = red[0] * (1.0f / DM_);
    __syncthreads();

    float sq = 0.f;
#pragma unroll
    for (int k = 0; k < 4; k++) { float d = v[k] - mean; sq += d * d; }
    red[t] = sq; __syncthreads();
    for (int o = 64; o > 0; o >>= 1) { if (t < o) red[t] += red[t + o]; __syncthreads(); }
    float var = red[0] * (1.0f / DM_);
    float inv = 1.0f / sqrtf(var + 1e-6f);

#pragma unroll
    for (int k = 0; k < 4; k++) {
        int d = t + 128 * k;
        g_qn[(long)r * DM_ + d] = (v[k] - mean) * inv * gamma[d] + beta[d];
    }
}

// ---------------- 3) TF32 tensor-core GEMM: C[2048x512] = A @ W ----------------
// MODE 0: q = qn@w_q * 1/8 -> g_q  | MODE 1: k | MODE 2: v | MODE 3: o@w_fc + s -> x_out
template<int MODE>
__global__ void k_gemm_tc(const float* __restrict__ W, float* __restrict__ out) {
    __shared__ float As[64][20];     // [m][k16], stride 20: conflict-free A-frags
    __shared__ float Ws[16][72];     // [k][n64], stride 72: conflict-free B-frags
    const float* A = (MODE == 0) ? g_qn : ((MODE == 3) ? g_o : g_s);

    int m0 = blockIdx.y * 64, n0 = blockIdx.x * 64;
    int tid = threadIdx.x;                 // 128
    int warp = tid >> 5, lane = tid & 31;
    int g = lane >> 2, t = lane & 3;
    int wm = (warp >> 1) * 32, wn = (warp & 1) * 32;

    float c[2][4][4] = {};

    for (int k0 = 0; k0 < DM_; k0 += 16) {
#pragma unroll
        for (int l = 0; l < 2; l++) {
            int idx = tid + l * 128;       // 256 float4s for A tile
            int m = idx >> 2, k4 = idx & 3;
            float4 v = *(const float4*)&A[(long)(m0 + m) * DM_ + k0 + k4 * 4];
            As[m][k4 * 4 + 0] = tf32r(v.x);
            As[m][k4 * 4 + 1] = tf32r(v.y);
            As[m][k4 * 4 + 2] = tf32r(v.z);
            As[m][k4 * 4 + 3] = tf32r(v.w);
        }
#pragma unroll
        for (int l = 0; l < 2; l++) {
            int idx = tid + l * 128;       // 256 float4s for W tile
            int k = idx >> 4, n4 = idx & 15;
            float4 v = *(const float4*)&W[(long)(k0 + k) * 512 + n0 + n4 * 4];
            Ws[k][n4 * 4 + 0] = tf32r(v.x);
            Ws[k][n4 * 4 + 1] = tf32r(v.y);
            Ws[k][n4 * 4 + 2] = tf32r(v.z);
            Ws[k][n4 * 4 + 3] = tf32r(v.w);
        }
        __syncthreads();
#pragma unroll
        for (int kk = 0; kk < 16; kk += 8) {
            uint32_t a[2][4], b[4][2];
#pragma unroll
            for (int mi = 0; mi < 2; mi++) {
                int r = wm + mi * 16;
                a[mi][0] = f2u(As[r + g][kk + t]);
                a[mi][1] = f2u(As[r + g + 8][kk + t]);
                a[mi][2] = f2u(As[r + g][kk + t + 4]);
                a[mi][3] = f2u(As[r + g + 8][kk + t + 4]);
            }
#pragma unroll
            for (int ni = 0; ni < 4; ni++) {
                int cc = wn + ni * 8 + g;
                b[ni][0] = f2u(Ws[kk + t][cc]);
                b[ni][1] = f2u(Ws[kk + t + 4][cc]);
            }
#pragma unroll
            for (int mi = 0; mi < 2; mi++)
#pragma unroll
                for (int ni = 0; ni < 4; ni++) mma_tf32(c[mi][ni], a[mi], b[ni]);
        }
        __syncthreads();
    }

#pragma unroll
    for (int mi = 0; mi < 2; mi++)
#pragma unroll
        for (int ni = 0; ni < 4; ni++)
#pragma unroll
            for (int e = 0; e < 4; e++) {
                int m = m0 + wm + mi * 16 + g + ((e >= 2) ? 8 : 0);
                int n = n0 + wn + ni * 8 + 2 * t + (e & 1);
                float val = c[mi][ni][e];
                if (MODE == 0) val *= 0.125f;
                if (MODE <= 2) {
                    int bb = m >> 10, ee = m & 1023;
                    int h = n >> 6, d = n & 63;
                    float* o = (MODE == 0) ? g_q : (MODE == 1) ? g_k : g_v;
                    o[(((long)(bb * H_ + h)) * E_ + ee) * 64 + d] = val;
                } else {
                    int bb = m >> 10, ee = m & 1023;
                    val += g_s[(long)m * DM_ + n];
                    out[((long)bb * DM_ + n) * E_ + ee] = val;
                }
            }
}

// ---------------- 4) qr[row][c] = qs_row . base_rpr[c] -------------------------
__global__ void k_qr(const float* __restrict__ rpr) {
    int row = blockIdx.x;
    int d = threadIdx.x;                       // 64 threads
    int lane = d & 31, w = d >> 5;
    float qv = g_q[(long)row * 64 + d];
    __shared__ float sh[2];
#pragma unroll
    for (int c = 0; c < 6; c++) {
        float p = qv * rpr[c * 64 + d];
#pragma unroll
        for (int o = 16; o; o >>= 1) p += __shfl_down_sync(0xffffffffu, p, o);
        if (lane == 0) sh[w] = p;
        __syncthreads();
        if (d == 0) g_qr[(long)row * 8 + c] = sh[0] + sh[1];
        __syncthreads();
    }
}

// ---------------- 5) logits = qs@k^T + qr[dist] (masked), TF32 mma -------------
__global__ void k_logits_tc(const int* __restrict__ dist, float* __restrict__ attn) {
    __shared__ float Qs[64][76];     // [i][d]
    __shared__ float Ks[64][76];     // [j][d]
    __shared__ float Qr[64][8];
    int bh = blockIdx.z;
    int b  = bh >> 3;
    int i0 = blockIdx.y * 64, j0 = blockIdx.x * 64;
    int tid = threadIdx.x;                 // 128
    int warp = tid >> 5, lane = tid & 31;
    int g = lane >> 2, t = lane & 3;
    int wm = (warp >> 1) * 32, wn = (warp & 1) * 32;

    const float* qp = g_q + ((long)bh * E_ + i0) * 64;
    const float* kp = g_k + ((long)bh * E_ + j0) * 64;
#pragma unroll
    for (int l = 0; l < 8; l++) {
        int idx = tid + l * 128;           // 1024 float4s
        int r = idx >> 4, c4 = (idx & 15) * 4;
        float4 v = *(const float4*)&qp[(long)r * 64 + c4];
        Qs[r][c4 + 0] = tf32r(v.x); Qs[r][c4 + 1] = tf32r(v.y);
        Qs[r][c4 + 2] = tf32r(v.z); Qs[r][c4 + 3] = tf32r(v.w);
        float4 u = *(const float4*)&kp[(long)r * 64 + c4];
        Ks[r][c4 + 0] = tf32r(u.x); Ks[r][c4 + 1] = tf32r(u.y);
        Ks[r][c4 + 2] = tf32r(u.z); Ks[r][c4 + 3] = tf32r(u.w);
    }
    {
        int r = tid >> 1, c4 = (tid & 1) * 4;  // 128 float4s = 512 floats
        float4 v = *(const float4*)&g_qr[((long)bh * E_ + i0 + r) * 8 + c4];
        Qr[r][c4 + 0] = v.x; Qr[r][c4 + 1] = v.y; Qr[r][c4 + 2] = v.z; Qr[r][c4 + 3] = v.w;
    }
    __syncthreads();

    float c[2][4][4] = {};
#pragma unroll
    for (int kk = 0; kk < 64; kk += 8) {
        uint32_t a[2][4], bfr[4][2];
#pragma unroll
        for (int mi = 0; mi < 2; mi++) {
            int r = wm + mi * 16;
            a[mi][0] = f2u(Qs[r + g][kk + t]);
            a[mi][1] = f2u(Qs[r + g + 8][kk + t]);
            a[mi][2] = f2u(Qs[r + g][kk + t + 4]);
            a[mi][3] = f2u(Qs[r + g + 8][kk + t + 4]);
        }
#pragma unroll
        for (int ni = 0; ni < 4; ni++) {
            int cc = wn + ni * 8 + g;
            bfr[ni][0] = f2u(Ks[cc][kk + t]);
            bfr[ni][1] = f2u(Ks[cc][kk + t + 4]);
        }
#pragma unroll
        for (int mi = 0; mi < 2; mi++)
#pragma unroll
            for (int ni = 0; ni < 4; ni++) mma_tf32(c[mi][ni], a[mi], bfr[ni]);
    }

#pragma unroll
    for (int mi = 0; mi < 2; mi++)
#pragma unroll
        for (int ni = 0; ni < 4; ni++)
#pragma unroll
            for (int e = 0; e < 4; e++) {
                int il = wm + mi * 16 + g + ((e >= 2) ? 8 : 0);
                int jl = wn + ni * 8 + 2 * t + (e & 1);
                int i = i0 + il, j = j0 + jl;
                int cd = dist[((long)b * E_ + i) * E_ + j];
                float v = (cd <= MAXN) ? c[mi][ni][e] + Qr[il][cd] : -1e9f;
                attn[((long)bh * E_ + i) * E_ + j] = v;
            }
}

// ---------------- 6) row softmax in place --------------------------------------
__global__ void k_softmax(float* __restrict__ attn) {
    long row = blockIdx.x;
    float4* p = (float4*)(attn + row * 1024);
    int t = threadIdx.x;                       // 256 threads, 1 float4 each
    float4 v = p[t];

    __shared__ float red[256];
    float m = fmaxf(fmaxf(v.x, v.y), fmaxf(v.z, v.w));
    red[t] = m; __syncthreads();
    for (int o = 128; o > 0; o >>= 1) { if (t < o) red[t] = fmaxf(red[t], red[t + o]); __syncthreads(); }
    m = red[0];
    __syncthreads();

    float ex = expf(v.x - m), ey = expf(v.y - m), ez = expf(v.z - m), ew = expf(v.w - m);
    red[t] = ex + ey + ez + ew; __syncthreads();
    for (int o = 128; o > 0; o >>= 1) { if (t < o) red[t] += red[t + o]; __syncthreads(); }
    float inv = 1.0f / red[0];
    p[t] = make_float4(ex * inv, ey * inv, ez * inv, ew * inv);
}

// ---------------- 7) out = attn @ v, TF32 mma ----------------------------------
__global__ void k_av_tc(const float* __restrict__ attn) {
    __shared__ float Ps[64][36];     // [i][j32]
    __shared__ float Vs[32][72];     // [j][d]
    int bh = blockIdx.y;
    int b = bh >> 3, h = bh & 7;
    int i0 = blockIdx.x * 64;
    int tid = threadIdx.x;
    int warp = tid >> 5, lane = tid & 31;
    int g = lane >> 2, t = lane & 3;
    int wm = (warp >> 1) * 32, wn = (warp & 1) * 32;

    const float* ap = attn + ((long)bh * E_ + i0) * E_;
    const float* vp = g_v + (long)bh * E_ * 64;
    float c[2][4][4] = {};

    for (int j0 = 0; j0 < E_; j0 += 32) {
#pragma unroll
        for (int l = 0; l < 4; l++) {
            int idx = tid + l * 128;           // 512 float4s of attn tile
            int r = idx >> 3, j4 = (idx & 7) * 4;
            float4 v = *(const float4*)&ap[(long)r * E_ + j0 + j4];
            Ps[r][j4 + 0] = tf32r(v.x); Ps[r][j4 + 1] = tf32r(v.y);
            Ps[r][j4 + 2] = tf32r(v.z); Ps[r][j4 + 3] = tf32r(v.w);
        }
#pragma unroll
        for (int l = 0; l < 4; l++) {
            int idx = tid + l * 128;           // 512 float4s of V tile
            int j = idx >> 4, d4 = (idx & 15) * 4;
            float4 v = *(const float4*)&vp[(long)(j0 + j) * 64 + d4];
            Vs[j][d4 + 0] = tf32r(v.x); Vs[j][d4 + 1] = tf32r(v.y);
            Vs[j][d4 + 2] = tf32r(v.z); Vs[j][d4 + 3] = tf32r(v.w);
        }
        __syncthreads();
#pragma unroll
        for (int kk = 0; kk < 32; kk += 8) {
            uint32_t a[2][4], bfr[4][2];
#pragma unroll
            for (int mi = 0; mi < 2; mi++) {
                int r = wm + mi * 16;
                a[mi][0] = f2u(Ps[r + g][kk + t]);
                a[mi][1] = f2u(Ps[r + g + 8][kk + t]);
                a[mi][2] = f2u(Ps[r + g][kk + t + 4]);
                a[mi][3] = f2u(Ps[r + g + 8][kk + t + 4]);
            }
#pragma unroll
            for (int ni = 0; ni < 4; ni++) {
                int cc = wn + ni * 8 + g;
                bfr[ni][0] = f2u(Vs[kk + t][cc]);
                bfr[ni][1] = f2u(Vs[kk + t + 4][cc]);
            }
#pragma unroll
            for (int mi = 0; mi < 2; mi++)
#pragma unroll
                for (int ni = 0; ni < 4; ni++) mma_tf32(c[mi][ni], a[mi], bfr[ni]);
        }
        __syncthreads();
    }

#pragma unroll
    for (int mi = 0; mi < 2; mi++)
#pragma unroll
        for (int ni = 0; ni < 4; ni++)
#pragma unroll
            for (int e = 0; e < 4; e++) {
                int i = i0 + wm + mi * 16 + g + ((e >= 2) ? 8 : 0);
                int d = wn + ni * 8 + 2 * t + (e & 1);
                g_o[((long)(b * E_ + i)) * 512 + h * 64 + d] = c[mi][ni][e];
            }
}

// ---------------- 8) attn_per_edge ---------------------------------------------
__global__ void k_zero() {
    int i = blockIdx.x * 256 + threadIdx.x;
    if (i < B_ * E_) { g_num[i] = 0.f; g_den[i] = 0.f; }
}

__global__ void k_ape_num(const float* __restrict__ attn) {
    int b = blockIdx.y;
    int row0 = blockIdx.x * 128;
    int t = threadIdx.x;                       // 256 threads, 1 float4/row each
    float4 s = make_float4(0.f, 0.f, 0.f, 0.f);
    const float4* base = (const float4*)(attn + ((long)b * (H_ * E_) + row0) * 1024);
    for (int rr = 0; rr < 128; rr++) {
        float4 v = base[(long)rr * 256 + t];
        s.x += v.x; s.y += v.y; s.z += v.z; s.w += v.w;
    }
    atomicAdd(&g_num[b * 1024 + t * 4 + 0], s.x);
    atomicAdd(&g_num[b * 1024 + t * 4 + 1], s.y);
    atomicAdd(&g_num[b * 1024 + t * 4 + 2], s.z);
    atomicAdd(&g_num[b * 1024 + t * 4 + 3], s.w);
}

__global__ void k_ape_den(const int* __restrict__ dist) {
    int b = blockIdx.y;
    int i0 = blockIdx.x * 128;
    int t = threadIdx.x;
    int cnt[4] = {};
    for (int rr = 0; rr < 128; rr++) {
        const int* p = dist + ((long)b * E_ + i0 + rr) * E_;
#pragma unroll
        for (int k = 0; k < 4; k++) cnt[k] += (p[t + 256 * k] <= MAXN) ? 1 : 0;
    }
#pragma unroll
    for (int k = 0; k < 4; k++) atomicAdd(&g_den[b * 1024 + t + 256 * k], (float)cnt[k]);
}

__global__ void k_ape_fin(float* __restrict__ out) {
    int i = blockIdx.x * 256 + threadIdx.x;
    if (i < B_ * E_) out[i] = g_num[i] / g_den[i];
}

// ---------------- launcher -----------------------------------------------------
extern "C" void kernel_launch(void* const* d_in, const int* in_sizes, int n_in,
                              void* d_out, int out_size) {
    const float* x    = (const float*)d_in[0];
    const int*   dist = (const int*)  d_in[1];
    const float* rpr  = (const float*)d_in[2];
    const float* w_q  = (const float*)d_in[3];
    const float* w_k  = (const float*)d_in[4];
    const float* w_v  = (const float*)d_in[5];
    const float* w_fc = (const float*)d_in[6];
    const float* ln_g = (const float*)d_in[7];
    const float* ln_b = (const float*)d_in[8];

    float* out  = (float*)d_out;
    float* attn = out + OFF_ATTN;
    float* ape  = out + OFF_APE;

    k_zero<<<8, 256>>>();
    k_transpose<<<dim3(E_ / 32, DM_ / 32, B_), dim3(32, 8)>>>(x);
    k_ln<<<B_ * E_, 128>>>(ln_g, ln_b);

    k_gemm_tc<0><<<dim3(8, 32), 128>>>(w_q, nullptr);
    k_gemm_tc<1><<<dim3(8, 32), 128>>>(w_k, nullptr);
    k_gemm_tc<2><<<dim3(8, 32), 128>>>(w_v, nullptr);

    k_qr<<<B_ * H_ * E_, 64>>>(rpr);

    k_logits_tc<<<dim3(E_ / 64, E_ / 64, B_ * H_), 128>>>(dist, attn);
    k_softmax<<<B_ * H_ * E_, 256>>>(attn);

    k_av_tc<<<dim3(E_ / 64, B_ * H_), 128>>>(attn);
    k_gemm_tc<3><<<dim3(8, 32), 128>>>(w_fc, out);

    k_ape_num<<<dim3(64, B_), 256>>>(attn);
    k_ape_den<<<dim3(8, B_), 256>>>(dist);
    k_ape_fin<<<8, 256>>>(ape);
}

// round 3
// speedup vs baseline: 2.3005x; 1.5225x over previous
#include <cuda_runtime.h>
#include <cstdint>
#include <math.h>

#define B_  2
#define E_  1024
#define DM_ 512
#define H_  8
#define DK_ 64
#define DV_ 64
#define MAXN 5

// d_out layout: x_out [B,DM,E] | attn [B,H,E,E] | attn_per_edge [B,E]
constexpr long OFF_ATTN = (long)B_ * DM_ * E_;
constexpr long OFF_APE  = OFF_ATTN + (long)B_ * H_ * E_ * E_;

// ---------------- scratch ------------------------------------------------------
__device__ float g_s [B_*E_*DM_];
__device__ float g_qn[B_*E_*DM_];
__device__ float g_q [B_*H_*E_*DK_];
__device__ float g_k [B_*H_*E_*DK_];
__device__ float g_v [B_*H_*E_*DV_];
__device__ float g_qr[B_*H_*E_*8];
__device__ float g_o [B_*E_*H_*DV_];
__device__ float g_num[B_*E_];
__device__ float g_den[B_*E_];

// ---------------- helpers ------------------------------------------------------
__device__ __forceinline__ float tf32r(float x) {
    asm("cvt.rna.tf32.f32 %0, %0;" : "+f"(x));
    return x;
}
__device__ __forceinline__ uint32_t f2u(float x) { return __float_as_uint(x); }

__device__ __forceinline__ void mma_tf32(float c[4], const uint32_t a[4], const uint32_t b[2]) {
    asm volatile(
        "mma.sync.aligned.m16n8k8.row.col.f32.tf32.tf32.f32 "
        "{%0,%1,%2,%3}, {%4,%5,%6,%7}, {%8,%9}, {%0,%1,%2,%3};"
        : "+f"(c[0]), "+f"(c[1]), "+f"(c[2]), "+f"(c[3])
        : "r"(a[0]), "r"(a[1]), "r"(a[2]), "r"(a[3]), "r"(b[0]), "r"(b[1]));
}

// ---------------- 1) transpose x[b][d][e] -> s[b][e][d] ------------------------
__global__ void k_transpose(const float* __restrict__ x) {
    __shared__ float tile[32][33];
    int b  = blockIdx.z;
    int e0 = blockIdx.x * 32, d0 = blockIdx.y * 32;
    int tx = threadIdx.x, ty = threadIdx.y;
#pragma unroll
    for (int l = 0; l < 4; l++) {
        int d = d0 + ty + l * 8;
        tile[ty + l * 8][tx] = x[((long)b * DM_ + d) * E_ + e0 + tx];
    }
    __syncthreads();
#pragma unroll
    for (int l = 0; l < 4; l++) {
        int e = e0 + ty + l * 8;
        g_s[((long)b * E_ + e) * DM_ + d0 + tx] = tile[tx][ty + l * 8];
    }
}

// ---------------- 2) LayerNorm -------------------------------------------------
__global__ void k_ln(const float* __restrict__ gamma, const float* __restrict__ beta) {
    int r = blockIdx.x, t = threadIdx.x;           // 128 threads
    const float* sp = g_s + (long)r * DM_;
    float v[4];
#pragma unroll
    for (int k = 0; k < 4; k++) v[k] = sp[t + 128 * k];

    __shared__ float red[128];
    float s = v[0] + v[1] + v[2] + v[3];
    red[t] = s; __syncthreads();
    for (int o = 64; o > 0; o >>= 1) { if (t < o) red[t] += red[t + o]; __syncthreads(); }
    float mean = red[0] * (1.0f / DM_);
    __syncthreads();

    float sq = 0.f;
#pragma unroll
    for (int k = 0; k < 4; k++) { float d = v[k] - mean; sq += d * d; }
    red[t] = sq; __syncthreads();
    for (int o = 64; o > 0; o >>= 1) { if (t < o) red[t] += red[t + o]; __syncthreads(); }
    float var = red[0] * (1.0f / DM_);
    float inv = 1.0f / sqrtf(var + 1e-6f);

#pragma unroll
    for (int k = 0; k < 4; k++) {
        int d = t + 128 * k;
        g_qn[(long)r * DM_ + d] = (v[k] - mean) * inv * gamma[d] + beta[d];
    }
}

// ---------------- 3) fused QKV GEMM (TF32), BM=128 BN=64 BK=32, 256 thr --------
// N axis 0..1535: [0,512)=Q from qn, [512,1024)=K from s, [1024,1536)=V from s
__global__ __launch_bounds__(256, 2)
void k_qkv(const float* __restrict__ w_q, const float* __restrict__ w_k,
           const float* __restrict__ w_v) {
    __shared__ float As[128][36];   // row-by-g pattern: bank = 4g+t, conflict-free
    __shared__ float Ws[32][72];    // row-by-t pattern: bank = 8t+g, conflict-free

    int m0 = blockIdx.y * 128;
    int nglob0 = blockIdx.x * 64;
    int sel = nglob0 >> 9;                 // 0=Q,1=K,2=V (64 | 512)
    int n0 = nglob0 & 511;
    const float* A = (sel == 0) ? g_qn : g_s;
    const float* W = (sel == 0) ? w_q : (sel == 1) ? w_k : w_v;

    int tid = threadIdx.x;                 // 256
    int warp = tid >> 5, lane = tid & 31;
    int g = lane >> 2, t = lane & 3;
    int wm = (warp >> 1) * 32, wn = (warp & 1) * 32;

    float c[2][4][4] = {};

    for (int k0 = 0; k0 < DM_; k0 += 32) {
#pragma unroll
        for (int l = 0; l < 4; l++) {           // A: 128x32 = 1024 float4
            int idx = tid + l * 256;
            int m = idx >> 3, k4 = (idx & 7) * 4;
            float4 v = *(const float4*)&A[(long)(m0 + m) * DM_ + k0 + k4];
            As[m][k4 + 0] = tf32r(v.x); As[m][k4 + 1] = tf32r(v.y);
            As[m][k4 + 2] = tf32r(v.z); As[m][k4 + 3] = tf32r(v.w);
        }
#pragma unroll
        for (int l = 0; l < 2; l++) {           // W: 32x64 = 512 float4
            int idx = tid + l * 256;
            int k = idx >> 4, n4 = (idx & 15) * 4;
            float4 v = *(const float4*)&W[(long)(k0 + k) * 512 + n0 + n4];
            Ws[k][n4 + 0] = tf32r(v.x); Ws[k][n4 + 1] = tf32r(v.y);
            Ws[k][n4 + 2] = tf32r(v.z); Ws[k][n4 + 3] = tf32r(v.w);
        }
        __syncthreads();
#pragma unroll
        for (int kk = 0; kk < 32; kk += 8) {
            uint32_t a[2][4], b[4][2];
#pragma unroll
            for (int mi = 0; mi < 2; mi++) {
                int r = wm + mi * 16;
                a[mi][0] = f2u(As[r + g][kk + t]);
                a[mi][1] = f2u(As[r + g + 8][kk + t]);
                a[mi][2] = f2u(As[r + g][kk + t + 4]);
                a[mi][3] = f2u(As[r + g + 8][kk + t + 4]);
            }
#pragma unroll
            for (int ni = 0; ni < 4; ni++) {
                int cc = wn + ni * 8 + g;
                b[ni][0] = f2u(Ws[kk + t][cc]);
                b[ni][1] = f2u(Ws[kk + t + 4][cc]);
            }
#pragma unroll
            for (int mi = 0; mi < 2; mi++)
#pragma unroll
                for (int ni = 0; ni < 4; ni++) mma_tf32(c[mi][ni], a[mi], b[ni]);
        }
        __syncthreads();
    }

    float* dst = (sel == 0) ? g_q : (sel == 1) ? g_k : g_v;
    float scale = (sel == 0) ? 0.125f : 1.0f;
#pragma unroll
    for (int mi = 0; mi < 2; mi++)
#pragma unroll
        for (int ni = 0; ni < 4; ni++)
#pragma unroll
            for (int e = 0; e < 4; e++) {
                int m = m0 + wm + mi * 16 + g + ((e >= 2) ? 8 : 0);
                int n = n0 + wn + ni * 8 + 2 * t + (e & 1);
                int bb = m >> 10, ee = m & 1023;
                int h = n >> 6, d = n & 63;
                dst[(((long)(bb * H_ + h)) * E_ + ee) * 64 + d] = c[mi][ni][e] * scale;
            }
}

// ---------------- 3b) fc GEMM: o @ w_fc + s -> x_out ---------------------------
__global__ __launch_bounds__(256, 2)
void k_fc(const float* __restrict__ W, float* __restrict__ out) {
    __shared__ float As[128][36];
    __shared__ float Ws[32][72];

    int m0 = blockIdx.y * 128, n0 = blockIdx.x * 64;
    int tid = threadIdx.x;
    int warp = tid >> 5, lane = tid & 31;
    int g = lane >> 2, t = lane & 3;
    int wm = (warp >> 1) * 32, wn = (warp & 1) * 32;

    float c[2][4][4] = {};

    for (int k0 = 0; k0 < DM_; k0 += 32) {
#pragma unroll
        for (int l = 0; l < 4; l++) {
            int idx = tid + l * 256;
            int m = idx >> 3, k4 = (idx & 7) * 4;
            float4 v = *(const float4*)&g_o[(long)(m0 + m) * DM_ + k0 + k4];
            As[m][k4 + 0] = tf32r(v.x); As[m][k4 + 1] = tf32r(v.y);
            As[m][k4 + 2] = tf32r(v.z); As[m][k4 + 3] = tf32r(v.w);
        }
#pragma unroll
        for (int l = 0; l < 2; l++) {
            int idx = tid + l * 256;
            int k = idx >> 4, n4 = (idx & 15) * 4;
            float4 v = *(const float4*)&W[(long)(k0 + k) * 512 + n0 + n4];
            Ws[k][n4 + 0] = tf32r(v.x); Ws[k][n4 + 1] = tf32r(v.y);
            Ws[k][n4 + 2] = tf32r(v.z); Ws[k][n4 + 3] = tf32r(v.w);
        }
        __syncthreads();
#pragma unroll
        for (int kk = 0; kk < 32; kk += 8) {
            uint32_t a[2][4], b[4][2];
#pragma unroll
            for (int mi = 0; mi < 2; mi++) {
                int r = wm + mi * 16;
                a[mi][0] = f2u(As[r + g][kk + t]);
                a[mi][1] = f2u(As[r + g + 8][kk + t]);
                a[mi][2] = f2u(As[r + g][kk + t + 4]);
                a[mi][3] = f2u(As[r + g + 8][kk + t + 4]);
            }
#pragma unroll
            for (int ni = 0; ni < 4; ni++) {
                int cc = wn + ni * 8 + g;
                b[ni][0] = f2u(Ws[kk + t][cc]);
                b[ni][1] = f2u(Ws[kk + t + 4][cc]);
            }
#pragma unroll
            for (int mi = 0; mi < 2; mi++)
#pragma unroll
                for (int ni = 0; ni < 4; ni++) mma_tf32(c[mi][ni], a[mi], b[ni]);
        }
        __syncthreads();
    }

#pragma unroll
    for (int mi = 0; mi < 2; mi++)
#pragma unroll
        for (int ni = 0; ni < 4; ni++)
#pragma unroll
            for (int e = 0; e < 4; e++) {
                int m = m0 + wm + mi * 16 + g + ((e >= 2) ? 8 : 0);
                int n = n0 + wn + ni * 8 + 2 * t + (e & 1);
                int bb = m >> 10, ee = m & 1023;
                float val = c[mi][ni][e] + g_s[(long)m * DM_ + n];
                out[((long)bb * DM_ + n) * E_ + ee] = val;
            }
}

// ---------------- 4) qr[row][c] = qs_row . base_rpr[c] -------------------------
__global__ void k_qr(const float* __restrict__ rpr) {
    int row = blockIdx.x;
    int d = threadIdx.x;                       // 64 threads
    int lane = d & 31, w = d >> 5;
    float qv = g_q[(long)row * 64 + d];
    __shared__ float sh[2];
#pragma unroll
    for (int c = 0; c < 6; c++) {
        float p = qv * rpr[c * 64 + d];
#pragma unroll
        for (int o = 16; o; o >>= 1) p += __shfl_down_sync(0xffffffffu, p, o);
        if (lane == 0) sh[w] = p;
        __syncthreads();
        if (d == 0) g_qr[(long)row * 8 + c] = sh[0] + sh[1];
        __syncthreads();
    }
}

// ---------------- 5) logits = qs@k^T + qr[dist] (masked) -----------------------
// BM=128 (i), BN=64 (j), k chunked 2x32
__global__ __launch_bounds__(256, 2)
void k_logits(const int* __restrict__ dist, float* __restrict__ attn) {
    __shared__ float Qs[128][36];
    __shared__ float Ks[64][36];
    __shared__ float Qr[128][8];
    int bh = blockIdx.z;
    int b  = bh >> 3;
    int i0 = blockIdx.y * 128, j0 = blockIdx.x * 64;
    int tid = threadIdx.x;                 // 256
    int warp = tid >> 5, lane = tid & 31;
    int g = lane >> 2, t = lane & 3;
    int wm = (warp >> 1) * 32, wn = (warp & 1) * 32;

    const float* qp = g_q + ((long)bh * E_ + i0) * 64;
    const float* kp = g_k + ((long)bh * E_ + j0) * 64;

    {   // Qr: 128 rows x 8 = 256 float4
        int r = tid >> 1, c4 = (tid & 1) * 4;
        float4 v = *(const float4*)&g_qr[((long)bh * E_ + i0 + r) * 8 + c4];
        Qr[r][c4 + 0] = v.x; Qr[r][c4 + 1] = v.y; Qr[r][c4 + 2] = v.z; Qr[r][c4 + 3] = v.w;
    }

    float c[2][4][4] = {};
#pragma unroll
    for (int k0 = 0; k0 < 64; k0 += 32) {
#pragma unroll
        for (int l = 0; l < 4; l++) {           // Q chunk: 128x32
            int idx = tid + l * 256;
            int r = idx >> 3, k4 = (idx & 7) * 4;
            float4 v = *(const float4*)&qp[(long)r * 64 + k0 + k4];
            Qs[r][k4 + 0] = tf32r(v.x); Qs[r][k4 + 1] = tf32r(v.y);
            Qs[r][k4 + 2] = tf32r(v.z); Qs[r][k4 + 3] = tf32r(v.w);
        }
#pragma unroll
        for (int l = 0; l < 2; l++) {           // K chunk: 64x32
            int idx = tid + l * 256;
            int r = idx >> 3, k4 = (idx & 7) * 4;
            float4 v = *(const float4*)&kp[(long)r * 64 + k0 + k4];
            Ks[r][k4 + 0] = tf32r(v.x); Ks[r][k4 + 1] = tf32r(v.y);
            Ks[r][k4 + 2] = tf32r(v.z); Ks[r][k4 + 3] = tf32r(v.w);
        }
        __syncthreads();
#pragma unroll
        for (int kk = 0; kk < 32; kk += 8) {
            uint32_t a[2][4], bfr[4][2];
#pragma unroll
            for (int mi = 0; mi < 2; mi++) {
                int r = wm + mi * 16;
                a[mi][0] = f2u(Qs[r + g][kk + t]);
                a[mi][1] = f2u(Qs[r + g + 8][kk + t]);
                a[mi][2] = f2u(Qs[r + g][kk + t + 4]);
                a[mi][3] = f2u(Qs[r + g + 8][kk + t + 4]);
            }
#pragma unroll
            for (int ni = 0; ni < 4; ni++) {
                int cc = wn + ni * 8 + g;
                bfr[ni][0] = f2u(Ks[cc][kk + t]);
                bfr[ni][1] = f2u(Ks[cc][kk + t + 4]);
            }
#pragma unroll
            for (int mi = 0; mi < 2; mi++)
#pragma unroll
                for (int ni = 0; ni < 4; ni++) mma_tf32(c[mi][ni], a[mi], bfr[ni]);
        }
        __syncthreads();
    }

#pragma unroll
    for (int mi = 0; mi < 2; mi++)
#pragma unroll
        for (int ni = 0; ni < 4; ni++)
#pragma unroll
            for (int e = 0; e < 4; e++) {
                int il = wm + mi * 16 + g + ((e >= 2) ? 8 : 0);
                int jl = wn + ni * 8 + 2 * t + (e & 1);
                int i = i0 + il, j = j0 + jl;
                int cd = dist[((long)b * E_ + i) * E_ + j];
                float v = (cd <= MAXN) ? c[mi][ni][e] + Qr[il][cd] : -1e9f;
                attn[((long)bh * E_ + i) * E_ + j] = v;
            }
}

// ---------------- 6) warp-per-row softmax in place -----------------------------
__global__ void k_softmax(float* __restrict__ attn) {
    long row = (long)blockIdx.x * 4 + (threadIdx.x >> 5);
    int lane = threadIdx.x & 31;
    float4* p = (float4*)(attn + row * 1024);

    float4 v[8];
#pragma unroll
    for (int k = 0; k < 8; k++) v[k] = p[lane + 32 * k];

    float m = -1e30f;
#pragma unroll
    for (int k = 0; k < 8; k++)
        m = fmaxf(m, fmaxf(fmaxf(v[k].x, v[k].y), fmaxf(v[k].z, v[k].w)));
#pragma unroll
    for (int o = 16; o; o >>= 1) m = fmaxf(m, __shfl_xor_sync(0xffffffffu, m, o));

    float s = 0.f;
#pragma unroll
    for (int k = 0; k < 8; k++) {
        v[k].x = __expf(v[k].x - m); v[k].y = __expf(v[k].y - m);
        v[k].z = __expf(v[k].z - m); v[k].w = __expf(v[k].w - m);
        s += v[k].x + v[k].y + v[k].z + v[k].w;
    }
#pragma unroll
    for (int o = 16; o; o >>= 1) s += __shfl_xor_sync(0xffffffffu, s, o);
    float inv = 1.0f / s;
#pragma unroll
    for (int k = 0; k < 8; k++) {
        v[k].x *= inv; v[k].y *= inv; v[k].z *= inv; v[k].w *= inv;
        p[lane + 32 * k] = v[k];
    }
}

// ---------------- 7) out = attn @ v --------------------------------------------
__global__ __launch_bounds__(256, 2)
void k_av(const float* __restrict__ attn) {
    __shared__ float Ps[128][36];
    __shared__ float Vs[32][72];
    int bh = blockIdx.y;
    int b = bh >> 3, h = bh & 7;
    int i0 = blockIdx.x * 128;
    int tid = threadIdx.x;
    int warp = tid >> 5, lane = tid & 31;
    int g = lane >> 2, t = lane & 3;
    int wm = (warp >> 1) * 32, wn = (warp & 1) * 32;

    const float* ap = attn + ((long)bh * E_ + i0) * E_;
    const float* vp = g_v + (long)bh * E_ * 64;
    float c[2][4][4] = {};

    for (int j0 = 0; j0 < E_; j0 += 32) {
#pragma unroll
        for (int l = 0; l < 4; l++) {           // attn tile 128x32
            int idx = tid + l * 256;
            int r = idx >> 3, j4 = (idx & 7) * 4;
            float4 v = *(const float4*)&ap[(long)r * E_ + j0 + j4];
            Ps[r][j4 + 0] = tf32r(v.x); Ps[r][j4 + 1] = tf32r(v.y);
            Ps[r][j4 + 2] = tf32r(v.z); Ps[r][j4 + 3] = tf32r(v.w);
        }
#pragma unroll
        for (int l = 0; l < 2; l++) {           // V tile 32x64
            int idx = tid + l * 256;
            int j = idx >> 4, d4 = (idx & 15) * 4;
            float4 v = *(const float4*)&vp[(long)(j0 + j) * 64 + d4];
            Vs[j][d4 + 0] = tf32r(v.x); Vs[j][d4 + 1] = tf32r(v.y);
            Vs[j][d4 + 2] = tf32r(v.z); Vs[j][d4 + 3] = tf32r(v.w);
        }
        __syncthreads();
#pragma unroll
        for (int kk = 0; kk < 32; kk += 8) {
            uint32_t a[2][4], bfr[4][2];
#pragma unroll
            for (int mi = 0; mi < 2; mi++) {
                int r = wm + mi * 16;
                a[mi][0] = f2u(Ps[r + g][kk + t]);
                a[mi][1] = f2u(Ps[r + g + 8][kk + t]);
                a[mi][2] = f2u(Ps[r + g][kk + t + 4]);
                a[mi][3] = f2u(Ps[r + g + 8][kk + t + 4]);
            }
#pragma unroll
            for (int ni = 0; ni < 4; ni++) {
                int cc = wn + ni * 8 + g;
                bfr[ni][0] = f2u(Vs[kk + t][cc]);
                bfr[ni][1] = f2u(Vs[kk + t + 4][cc]);
            }
#pragma unroll
            for (int mi = 0; mi < 2; mi++)
#pragma unroll
                for (int ni = 0; ni < 4; ni++) mma_tf32(c[mi][ni], a[mi], bfr[ni]);
        }
        __syncthreads();
    }

#pragma unroll
    for (int mi = 0; mi < 2; mi++)
#pragma unroll
        for (int ni = 0; ni < 4; ni++)
#pragma unroll
            for (int e = 0; e < 4; e++) {
                int i = i0 + wm + mi * 16 + g + ((e >= 2) ? 8 : 0);
                int d = wn + ni * 8 + 2 * t + (e & 1);
                g_o[((long)(b * E_ + i)) * 512 + h * 64 + d] = c[mi][ni][e];
            }
}

// ---------------- 8) attn_per_edge ---------------------------------------------
__global__ void k_zero() {
    int i = blockIdx.x * 256 + threadIdx.x;
    if (i < B_ * E_) { g_num[i] = 0.f; g_den[i] = 0.f; }
}

__global__ void k_ape_num(const float* __restrict__ attn) {
    int b = blockIdx.y;
    int row0 = blockIdx.x * 128;
    int t = threadIdx.x;                       // 256 threads, 1 float4/row each
    float4 s = make_float4(0.f, 0.f, 0.f, 0.f);
    const float4* base = (const float4*)(attn + ((long)b * (H_ * E_) + row0) * 1024);
    for (int rr = 0; rr < 128; rr++) {
        float4 v = base[(long)rr * 256 + t];
        s.x += v.x; s.y += v.y; s.z += v.z; s.w += v.w;
    }
    atomicAdd(&g_num[b * 1024 + t * 4 + 0], s.x);
    atomicAdd(&g_num[b * 1024 + t * 4 + 1], s.y);
    atomicAdd(&g_num[b * 1024 + t * 4 + 2], s.z);
    atomicAdd(&g_num[b * 1024 + t * 4 + 3], s.w);
}

__global__ void k_ape_den(const int* __restrict__ dist) {
    int b = blockIdx.y;
    int i0 = blockIdx.x * 128;
    int t = threadIdx.x;
    int cnt[4] = {};
    for (int rr = 0; rr < 128; rr++) {
        const int* p = dist + ((long)b * E_ + i0 + rr) * E_;
#pragma unroll
        for (int k = 0; k < 4; k++) cnt[k] += (p[t + 256 * k] <= MAXN) ? 1 : 0;
    }
#pragma unroll
    for (int k = 0; k < 4; k++) atomicAdd(&g_den[b * 1024 + t + 256 * k], (float)cnt[k]);
}

__global__ void k_ape_fin(float* __restrict__ out) {
    int i = blockIdx.x * 256 + threadIdx.x;
    if (i < B_ * E_) out[i] = g_num[i] / g_den[i];
}

// ---------------- launcher -----------------------------------------------------
extern "C" void kernel_launch(void* const* d_in, const int* in_sizes, int n_in,
                              void* d_out, int out_size) {
    const float* x    = (const float*)d_in[0];
    const int*   dist = (const int*)  d_in[1];
    const float* rpr  = (const float*)d_in[2];
    const float* w_q  = (const float*)d_in[3];
    const float* w_k  = (const float*)d_in[4];
    const float* w_v  = (const float*)d_in[5];
    const float* w_fc = (const float*)d_in[6];
    const float* ln_g = (const float*)d_in[7];
    const float* ln_b = (const float*)d_in[8];

    float* out  = (float*)d_out;
    float* attn = out + OFF_ATTN;
    float* ape  = out + OFF_APE;

    k_zero<<<8, 256>>>();
    k_transpose<<<dim3(E_ / 32, DM_ / 32, B_), dim3(32, 8)>>>(x);
    k_ln<<<B_ * E_, 128>>>(ln_g, ln_b);

    k_qkv<<<dim3(24, 16), 256>>>(w_q, w_k, w_v);

    k_qr<<<B_ * H_ * E_, 64>>>(rpr);

    k_logits<<<dim3(E_ / 64, E_ / 128, B_ * H_), 256>>>(dist, attn);
    k_softmax<<<(B_ * H_ * E_) / 4, 128>>>(attn);

    k_av<<<dim3(E_ / 128, B_ * H_), 256>>>(attn);
    k_fc<<<dim3(8, 16), 256>>>(w_fc, out);

    k_ape_num<<<dim3(64, B_), 256>>>(attn);
    k_ape_den<<<dim3(8, B_), 256>>>(dist);
    k_ape_fin<<<8, 256>>>(ape);
}

// round 16
// speedup vs baseline: 2.6286x; 1.1426x over previous
#include <cuda_runtime.h>
#include <cstdint>
#include <math.h>

#define B_  2
#define E_  1024
#define DM_ 512
#define H_  8
#define DK_ 64
#define DV_ 64
#define MAXN 5

// d_out layout: x_out [B,DM,E] | attn [B,H,E,E] | attn_per_edge [B,E]
constexpr long OFF_ATTN = (long)B_ * DM_ * E_;
constexpr long OFF_APE  = OFF_ATTN + (long)B_ * H_ * E_ * E_;

// ---------------- scratch ------------------------------------------------------
__device__ float g_s [B_*E_*DM_];
__device__ float g_qn[B_*E_*DM_];
__device__ float g_q [B_*H_*E_*DK_];
__device__ float g_k [B_*H_*E_*DK_];
__device__ float g_v [B_*H_*E_*DV_];
__device__ float g_qr[B_*H_*E_*8];
__device__ float g_o [B_*E_*H_*DV_];
__device__ float g_rsum[B_*H_*E_];
__device__ float g_num[B_*E_];
__device__ float g_den[B_*E_];

// ---------------- helpers ------------------------------------------------------
__device__ __forceinline__ float tf32r(float x) {
    asm("cvt.rna.tf32.f32 %0, %0;" : "+f"(x));
    return x;
}
__device__ __forceinline__ uint32_t f2u(float x) { return __float_as_uint(x); }
__device__ __forceinline__ uint32_t ldtf(const float* p) { return f2u(tf32r(*p)); }

__device__ __forceinline__ void mma_tf32(float c[4], const uint32_t a[4], const uint32_t b[2]) {
    asm volatile(
        "mma.sync.aligned.m16n8k8.row.col.f32.tf32.tf32.f32 "
        "{%0,%1,%2,%3}, {%4,%5,%6,%7}, {%8,%9}, {%0,%1,%2,%3};"
        : "+f"(c[0]), "+f"(c[1]), "+f"(c[2]), "+f"(c[3])
        : "r"(a[0]), "r"(a[1]), "r"(a[2]), "r"(a[3]), "r"(b[0]), "r"(b[1]));
}

__device__ __forceinline__ void cp16(float* smem_dst, const float* gsrc) {
    uint32_t s = (uint32_t)__cvta_generic_to_shared(smem_dst);
    asm volatile("cp.async.cg.shared.global [%0], [%1], 16;" :: "r"(s), "l"(gsrc));
}
__device__ __forceinline__ void cp_commit() { asm volatile("cp.async.commit_group;"); }
__device__ __forceinline__ void cp_wait1()  { asm volatile("cp.async.wait_group 1;"); }
__device__ __forceinline__ void cp_wait0()  { asm volatile("cp.async.wait_group 0;"); }

constexpr int ASZ = 128 * 36;   // A tile floats (stride 36)
constexpr int WSZ = 32 * 72;    // W tile floats (stride 72)
constexpr int DBUF_BYTES = 2 * (ASZ + WSZ) * 4;   // 55296

// ---------------- 0) zero scratch ----------------------------------------------
__global__ void k_zero() {
    long i = (long)blockIdx.x * 256 + threadIdx.x;
    if (i < B_ * E_)        { g_num[i] = 0.f; g_den[i] = 0.f; }
    if (i < B_ * H_ * E_)   g_rsum[i] = 0.f;
    if (i < (long)B_ * E_ * DM_) g_o[i] = 0.f;
}

// ---------------- 1) transpose x[b][d][e] -> s[b][e][d] ------------------------
__global__ void k_transpose(const float* __restrict__ x) {
    __shared__ float tile[32][33];
    int b  = blockIdx.z;
    int e0 = blockIdx.x * 32, d0 = blockIdx.y * 32;
    int tx = threadIdx.x, ty = threadIdx.y;
#pragma unroll
    for (int l = 0; l < 4; l++) {
        int d = d0 + ty + l * 8;
        tile[ty + l * 8][tx] = x[((long)b * DM_ + d) * E_ + e0 + tx];
    }
    __syncthreads();
#pragma unroll
    for (int l = 0; l < 4; l++) {
        int e = e0 + ty + l * 8;
        g_s[((long)b * E_ + e) * DM_ + d0 + tx] = tile[tx][ty + l * 8];
    }
}

// ---------------- 2) LayerNorm -------------------------------------------------
__global__ void k_ln(const float* __restrict__ gamma, const float* __restrict__ beta) {
    int r = blockIdx.x, t = threadIdx.x;           // 128 threads
    const float* sp = g_s + (long)r * DM_;
    float v[4];
#pragma unroll
    for (int k = 0; k < 4; k++) v[k] = sp[t + 128 * k];

    __shared__ float red[128];
    float s = v[0] + v[1] + v[2] + v[3];
    red[t] = s; __syncthreads();
    for (int o = 64; o > 0; o >>= 1) { if (t < o) red[t] += red[t + o]; __syncthreads(); }
    float mean = red[0] * (1.0f / DM_);
    __syncthreads();

    float sq = 0.f;
#pragma unroll
    for (int k = 0; k < 4; k++) { float d = v[k] - mean; sq += d * d; }
    red[t] = sq; __syncthreads();
    for (int o = 64; o > 0; o >>= 1) { if (t < o) red[t] += red[t + o]; __syncthreads(); }
    float var = red[0] * (1.0f / DM_);
    float inv = 1.0f / sqrtf(var + 1e-6f);

#pragma unroll
    for (int k = 0; k < 4; k++) {
        int d = t + 128 * k;
        g_qn[(long)r * DM_ + d] = (v[k] - mean) * inv * gamma[d] + beta[d];
    }
}

// ---------------- 3) fused QKV GEMM, cp.async double-buffered -------------------
__global__ __launch_bounds__(256, 2)
void k_qkv(const float* __restrict__ w_q, const float* __restrict__ w_k,
           const float* __restrict__ w_v) {
    extern __shared__ float sm[];

    int m0 = blockIdx.y * 128;
    int nglob0 = blockIdx.x * 64;
    int sel = nglob0 >> 9;                 // 0=Q,1=K,2=V
    int n0 = nglob0 & 511;
    const float* A = (sel == 0) ? g_qn : g_s;
    const float* W = (sel == 0) ? w_q : (sel == 1) ? w_k : w_v;

    int tid = threadIdx.x;
    int warp = tid >> 5, lane = tid & 31;
    int g = lane >> 2, t = lane & 3;
    int wm = (warp >> 1) * 32, wn = (warp & 1) * 32;

    auto load_stage = [&](int k0, int st) {
        float* a = sm + st * (ASZ + WSZ);
        float* w = a + ASZ;
#pragma unroll
        for (int l = 0; l < 4; l++) {
            int idx = tid + l * 256;
            int m = idx >> 3, k4 = (idx & 7) * 4;
            cp16(&a[m * 36 + k4], &A[(long)(m0 + m) * DM_ + k0 + k4]);
        }
#pragma unroll
        for (int l = 0; l < 2; l++) {
            int idx = tid + l * 256;
            int k = idx >> 4, n4 = (idx & 15) * 4;
            cp16(&w[k * 72 + n4], &W[(long)(k0 + k) * 512 + n0 + n4]);
        }
        cp_commit();
    };

    float c[2][4][4] = {};
    load_stage(0, 0);

    for (int it = 0; it < 16; it++) {
        int cur = it & 1;
        if (it + 1 < 16) { load_stage((it + 1) * 32, cur ^ 1); cp_wait1(); }
        else cp_wait0();
        __syncthreads();

        const float* As = sm + cur * (ASZ + WSZ);
        const float* Ws = As + ASZ;
#pragma unroll
        for (int kk = 0; kk < 32; kk += 8) {
            uint32_t a[2][4], b[4][2];
#pragma unroll
            for (int mi = 0; mi < 2; mi++) {
                int r = wm + mi * 16;
                a[mi][0] = ldtf(&As[(r + g) * 36 + kk + t]);
                a[mi][1] = ldtf(&As[(r + g + 8) * 36 + kk + t]);
                a[mi][2] = ldtf(&As[(r + g) * 36 + kk + t + 4]);
                a[mi][3] = ldtf(&As[(r + g + 8) * 36 + kk + t + 4]);
            }
#pragma unroll
            for (int ni = 0; ni < 4; ni++) {
                int cc = wn + ni * 8 + g;
                b[ni][0] = ldtf(&Ws[(kk + t) * 72 + cc]);
                b[ni][1] = ldtf(&Ws[(kk + t + 4) * 72 + cc]);
            }
#pragma unroll
            for (int mi = 0; mi < 2; mi++)
#pragma unroll
                for (int ni = 0; ni < 4; ni++) mma_tf32(c[mi][ni], a[mi], b[ni]);
        }
        __syncthreads();
    }

    float* dst = (sel == 0) ? g_q : (sel == 1) ? g_k : g_v;
    float scale = (sel == 0) ? 0.125f : 1.0f;
#pragma unroll
    for (int mi = 0; mi < 2; mi++)
#pragma unroll
        for (int ni = 0; ni < 4; ni++)
#pragma unroll
            for (int e = 0; e < 4; e++) {
                int m = m0 + wm + mi * 16 + g + ((e >= 2) ? 8 : 0);
                int n = n0 + wn + ni * 8 + 2 * t + (e & 1);
                int bb = m >> 10, ee = m & 1023;
                int h = n >> 6, d = n & 63;
                dst[(((long)(bb * H_ + h)) * E_ + ee) * 64 + d] = c[mi][ni][e] * scale;
            }
}

// ---------------- 3b) fc GEMM: o @ w_fc + s -> x_out, cp.async ------------------
__global__ __launch_bounds__(256, 2)
void k_fc(const float* __restrict__ W, float* __restrict__ out) {
    extern __shared__ float sm[];
    int m0 = blockIdx.y * 128, n0 = blockIdx.x * 64;
    int tid = threadIdx.x;
    int warp = tid >> 5, lane = tid & 31;
    int g = lane >> 2, t = lane & 3;
    int wm = (warp >> 1) * 32, wn = (warp & 1) * 32;

    auto load_stage = [&](int k0, int st) {
        float* a = sm + st * (ASZ + WSZ);
        float* w = a + ASZ;
#pragma unroll
        for (int l = 0; l < 4; l++) {
            int idx = tid + l * 256;
            int m = idx >> 3, k4 = (idx & 7) * 4;
            cp16(&a[m * 36 + k4], &g_o[(long)(m0 + m) * DM_ + k0 + k4]);
        }
#pragma unroll
        for (int l = 0; l < 2; l++) {
            int idx = tid + l * 256;
            int k = idx >> 4, n4 = (idx & 15) * 4;
            cp16(&w[k * 72 + n4], &W[(long)(k0 + k) * 512 + n0 + n4]);
        }
        cp_commit();
    };

    float c[2][4][4] = {};
    load_stage(0, 0);

    for (int it = 0; it < 16; it++) {
        int cur = it & 1;
        if (it + 1 < 16) { load_stage((it + 1) * 32, cur ^ 1); cp_wait1(); }
        else cp_wait0();
        __syncthreads();

        const float* As = sm + cur * (ASZ + WSZ);
        const float* Ws = As + ASZ;
#pragma unroll
        for (int kk = 0; kk < 32; kk += 8) {
            uint32_t a[2][4], b[4][2];
#pragma unroll
            for (int mi = 0; mi < 2; mi++) {
                int r = wm + mi * 16;
                a[mi][0] = ldtf(&As[(r + g) * 36 + kk + t]);
                a[mi][1] = ldtf(&As[(r + g + 8) * 36 + kk + t]);
                a[mi][2] = ldtf(&As[(r + g) * 36 + kk + t + 4]);
                a[mi][3] = ldtf(&As[(r + g + 8) * 36 + kk + t + 4]);
            }
#pragma unroll
            for (int ni = 0; ni < 4; ni++) {
                int cc = wn + ni * 8 + g;
                b[ni][0] = ldtf(&Ws[(kk + t) * 72 + cc]);
                b[ni][1] = ldtf(&Ws[(kk + t + 4) * 72 + cc]);
            }
#pragma unroll
            for (int mi = 0; mi < 2; mi++)
#pragma unroll
                for (int ni = 0; ni < 4; ni++) mma_tf32(c[mi][ni], a[mi], b[ni]);
        }
        __syncthreads();
    }

#pragma unroll
    for (int mi = 0; mi < 2; mi++)
#pragma unroll
        for (int ni = 0; ni < 4; ni++)
#pragma unroll
            for (int e = 0; e < 4; e++) {
                int m = m0 + wm + mi * 16 + g + ((e >= 2) ? 8 : 0);
                int n = n0 + wn + ni * 8 + 2 * t + (e & 1);
                int bb = m >> 10, ee = m & 1023;
                float val = c[mi][ni][e] + g_s[(long)m * DM_ + n];
                out[((long)bb * DM_ + n) * E_ + ee] = val;
            }
}

// ---------------- 4) qr[row][c] = qs_row . base_rpr[c] -------------------------
__global__ void k_qr(const float* __restrict__ rpr) {
    int row = blockIdx.x;
    int d = threadIdx.x;                       // 64 threads
    int lane = d & 31, w = d >> 5;
    float qv = g_q[(long)row * 64 + d];
    __shared__ float sh[2];
#pragma unroll
    for (int c = 0; c < 6; c++) {
        float p = qv * rpr[c * 64 + d];
#pragma unroll
        for (int o = 16; o; o >>= 1) p += __shfl_down_sync(0xffffffffu, p, o);
        if (lane == 0) sh[w] = p;
        __syncthreads();
        if (d == 0) g_qr[(long)row * 8 + c] = sh[0] + sh[1];
        __syncthreads();
    }
}

// ---------------- 5) unnorm attn = exp(qs@k^T + qr[dist]) masked; row sums -----
__global__ __launch_bounds__(256, 2)
void k_logits(const int* __restrict__ dist, float* __restrict__ attn) {
    __shared__ float Qs[128][36];
    __shared__ float Ks[64][36];
    __shared__ float Qr[128][8];
    int bh = blockIdx.z;
    int b  = bh >> 3;
    int i0 = blockIdx.y * 128, j0 = blockIdx.x * 64;
    int tid = threadIdx.x;                 // 256
    int warp = tid >> 5, lane = tid & 31;
    int g = lane >> 2, t = lane & 3;
    int wm = (warp >> 1) * 32, wn = (warp & 1) * 32;

    const float* qp = g_q + ((long)bh * E_ + i0) * 64;
    const float* kp = g_k + ((long)bh * E_ + j0) * 64;

    {   // Qr: 128 rows x 8 = 256 float4
        int r = tid >> 1, c4 = (tid & 1) * 4;
        float4 v = *(const float4*)&g_qr[((long)bh * E_ + i0 + r) * 8 + c4];
        Qr[r][c4 + 0] = v.x; Qr[r][c4 + 1] = v.y; Qr[r][c4 + 2] = v.z; Qr[r][c4 + 3] = v.w;
    }

    float c[2][4][4] = {};
#pragma unroll
    for (int k0 = 0; k0 < 64; k0 += 32) {
#pragma unroll
        for (int l = 0; l < 4; l++) {           // Q chunk: 128x32
            int idx = tid + l * 256;
            int r = idx >> 3, k4 = (idx & 7) * 4;
            float4 v = *(const float4*)&qp[(long)r * 64 + k0 + k4];
            Qs[r][k4 + 0] = tf32r(v.x); Qs[r][k4 + 1] = tf32r(v.y);
            Qs[r][k4 + 2] = tf32r(v.z); Qs[r][k4 + 3] = tf32r(v.w);
        }
#pragma unroll
        for (int l = 0; l < 2; l++) {           // K chunk: 64x32
            int idx = tid + l * 256;
            int r = idx >> 3, k4 = (idx & 7) * 4;
            float4 v = *(const float4*)&kp[(long)r * 64 + k0 + k4];
            Ks[r][k4 + 0] = tf32r(v.x); Ks[r][k4 + 1] = tf32r(v.y);
            Ks[r][k4 + 2] = tf32r(v.z); Ks[r][k4 + 3] = tf32r(v.w);
        }
        __syncthreads();
#pragma unroll
        for (int kk = 0; kk < 32; kk += 8) {
            uint32_t a[2][4], bfr[4][2];
#pragma unroll
            for (int mi = 0; mi < 2; mi++) {
                int r = wm + mi * 16;
                a[mi][0] = f2u(Qs[r + g][kk + t]);
                a[mi][1] = f2u(Qs[r + g + 8][kk + t]);
                a[mi][2] = f2u(Qs[r + g][kk + t + 4]);
                a[mi][3] = f2u(Qs[r + g + 8][kk + t + 4]);
            }
#pragma unroll
            for (int ni = 0; ni < 4; ni++) {
                int cc = wn + ni * 8 + g;
                bfr[ni][0] = f2u(Ks[cc][kk + t]);
                bfr[ni][1] = f2u(Ks[cc][kk + t + 4]);
            }
#pragma unroll
            for (int mi = 0; mi < 2; mi++)
#pragma unroll
                for (int ni = 0; ni < 4; ni++) mma_tf32(c[mi][ni], a[mi], bfr[ni]);
        }
        __syncthreads();
    }

    float rsum[2][2] = {};
#pragma unroll
    for (int mi = 0; mi < 2; mi++)
#pragma unroll
        for (int ni = 0; ni < 4; ni++)
#pragma unroll
            for (int e = 0; e < 4; e++) {
                int ep = e >> 1;
                int il = wm + mi * 16 + g + ep * 8;
                int jl = wn + ni * 8 + 2 * t + (e & 1);
                int i = i0 + il, j = j0 + jl;
                int cd = dist[((long)b * E_ + i) * E_ + j];
                float v = (cd <= MAXN) ? __expf(c[mi][ni][e] + Qr[il][min(cd, MAXN)]) : 0.f;
                attn[((long)bh * E_ + i) * E_ + j] = v;
                rsum[mi][ep] += v;
            }
#pragma unroll
    for (int mi = 0; mi < 2; mi++)
#pragma unroll
        for (int ep = 0; ep < 2; ep++) {
            float s = rsum[mi][ep];
            s += __shfl_xor_sync(0xffffffffu, s, 1);
            s += __shfl_xor_sync(0xffffffffu, s, 2);
            if (t == 0)
                atomicAdd(&g_rsum[(long)bh * E_ + i0 + wm + mi * 16 + g + ep * 8], s);
        }
}

// ---------------- 6) out = attnU @ v * inv_rsum, split-K=2, cp.async ------------
__global__ __launch_bounds__(256, 2)
void k_av(const float* __restrict__ attn) {
    extern __shared__ float sm[];
    int bh = blockIdx.y;
    int b = bh >> 3, h = bh & 7;
    int i0 = blockIdx.x * 128;
    int jbase = blockIdx.z * 512;
    int tid = threadIdx.x;
    int warp = tid >> 5, lane = tid & 31;
    int g = lane >> 2, t = lane & 3;
    int wm = (warp >> 1) * 32, wn = (warp & 1) * 32;

    const float* ap = attn + ((long)bh * E_ + i0) * E_;
    const float* vp = g_v + (long)bh * E_ * 64;

    auto load_stage = [&](int j0, int st) {
        float* P = sm + st * (ASZ + WSZ);
        float* V = P + ASZ;
#pragma unroll
        for (int l = 0; l < 4; l++) {
            int idx = tid + l * 256;
            int r = idx >> 3, j4 = (idx & 7) * 4;
            cp16(&P[r * 36 + j4], &ap[(long)r * E_ + j0 + j4]);
        }
#pragma unroll
        for (int l = 0; l < 2; l++) {
            int idx = tid + l * 256;
            int j = idx >> 4, d4 = (idx & 15) * 4;
            cp16(&V[j * 72 + d4], &vp[(long)(j0 + j) * 64 + d4]);
        }
        cp_commit();
    };

    float c[2][4][4] = {};
    load_stage(jbase, 0);

    for (int it = 0; it < 16; it++) {
        int cur = it & 1;
        if (it + 1 < 16) { load_stage(jbase + (it + 1) * 32, cur ^ 1); cp_wait1(); }
        else cp_wait0();
        __syncthreads();

        const float* Ps = sm + cur * (ASZ + WSZ);
        const float* Vs = Ps + ASZ;
#pragma unroll
        for (int kk = 0; kk < 32; kk += 8) {
            uint32_t a[2][4], bfr[4][2];
#pragma unroll
            for (int mi = 0; mi < 2; mi++) {
                int r = wm + mi * 16;
                a[mi][0] = ldtf(&Ps[(r + g) * 36 + kk + t]);
                a[mi][1] = ldtf(&Ps[(r + g + 8) * 36 + kk + t]);
                a[mi][2] = ldtf(&Ps[(r + g) * 36 + kk + t + 4]);
                a[mi][3] = ldtf(&Ps[(r + g + 8) * 36 + kk + t + 4]);
            }
#pragma unroll
            for (int ni = 0; ni < 4; ni++) {
                int cc = wn + ni * 8 + g;
                bfr[ni][0] = ldtf(&Vs[(kk + t) * 72 + cc]);
                bfr[ni][1] = ldtf(&Vs[(kk + t + 4) * 72 + cc]);
            }
#pragma unroll
            for (int mi = 0; mi < 2; mi++)
#pragma unroll
                for (int ni = 0; ni < 4; ni++) mma_tf32(c[mi][ni], a[mi], bfr[ni]);
        }
        __syncthreads();
    }

    float inv[2][2];
#pragma unroll
    for (int mi = 0; mi < 2; mi++)
#pragma unroll
        for (int ep = 0; ep < 2; ep++)
            inv[mi][ep] = 1.0f / g_rsum[(long)bh * E_ + i0 + wm + mi * 16 + g + ep * 8];

#pragma unroll
    for (int mi = 0; mi < 2; mi++)
#pragma unroll
        for (int ni = 0; ni < 4; ni++)
#pragma unroll
            for (int e = 0; e < 4; e++) {
                int ep = e >> 1;
                int i = i0 + wm + mi * 16 + g + ep * 8;
                int d = wn + ni * 8 + 2 * t + (e & 1);
                atomicAdd(&g_o[((long)(b * E_ + i)) * 512 + h * 64 + d],
                          c[mi][ni][e] * inv[mi][ep]);
            }
}

// ---------------- 7) normalize attn in place + ape column sums ------------------
__global__ void k_norm(float* __restrict__ attn) {
    __shared__ float inv[128];
    int b = blockIdx.y;
    int row0 = blockIdx.x * 128;               // rows within b: h*E+i, 8192 total
    int t = threadIdx.x;                       // 256
    if (t < 128) inv[t] = 1.0f / g_rsum[(long)b * (H_ * E_) + row0 + t];
    __syncthreads();

    float4* base = (float4*)(attn + ((long)b * (H_ * E_) + row0) * 1024);
    float4 s = make_float4(0.f, 0.f, 0.f, 0.f);
    for (int rr = 0; rr < 128; rr++) {
        float4 v = base[(long)rr * 256 + t];
        float iv = inv[rr];
        v.x *= iv; v.y *= iv; v.z *= iv; v.w *= iv;
        base[(long)rr * 256 + t] = v;
        s.x += v.x; s.y += v.y; s.z += v.z; s.w += v.w;
    }
    atomicAdd(&g_num[b * 1024 + t * 4 + 0], s.x);
    atomicAdd(&g_num[b * 1024 + t * 4 + 1], s.y);
    atomicAdd(&g_num[b * 1024 + t * 4 + 2], s.z);
    atomicAdd(&g_num[b * 1024 + t * 4 + 3], s.w);
}

// ---------------- 8) ape denominator + final ------------------------------------
__global__ void k_ape_den(const int* __restrict__ dist) {
    int b = blockIdx.y;
    int i0 = blockIdx.x * 128;
    int t = threadIdx.x;
    int cnt[4] = {};
    for (int rr = 0; rr < 128; rr++) {
        const int* p = dist + ((long)b * E_ + i0 + rr) * E_;
#pragma unroll
        for (int k = 0; k < 4; k++) cnt[k] += (p[t + 256 * k] <= MAXN) ? 1 : 0;
    }
#pragma unroll
    for (int k = 0; k < 4; k++) atomicAdd(&g_den[b * 1024 + t + 256 * k], (float)cnt[k]);
}

__global__ void k_ape_fin(float* __restrict__ out) {
    int i = blockIdx.x * 256 + threadIdx.x;
    if (i < B_ * E_) out[i] = g_num[i] / g_den[i];
}

// ---------------- launcher -----------------------------------------------------
extern "C" void kernel_launch(void* const* d_in, const int* in_sizes, int n_in,
                              void* d_out, int out_size) {
    const float* x    = (const float*)d_in[0];
    const int*   dist = (const int*)  d_in[1];
    const float* rpr  = (const float*)d_in[2];
    const float* w_q  = (const float*)d_in[3];
    const float* w_k  = (const float*)d_in[4];
    const float* w_v  = (const float*)d_in[5];
    const float* w_fc = (const float*)d_in[6];
    const float* ln_g = (const float*)d_in[7];
    const float* ln_b = (const float*)d_in[8];

    float* out  = (float*)d_out;
    float* attn = out + OFF_ATTN;
    float* ape  = out + OFF_APE;

    cudaFuncSetAttribute(k_qkv, cudaFuncAttributeMaxDynamicSharedMemorySize, DBUF_BYTES);
    cudaFuncSetAttribute(k_fc,  cudaFuncAttributeMaxDynamicSharedMemorySize, DBUF_BYTES);
    cudaFuncSetAttribute(k_av,  cudaFuncAttributeMaxDynamicSharedMemorySize, DBUF_BYTES);

    k_zero<<<4096, 256>>>();
    k_transpose<<<dim3(E_ / 32, DM_ / 32, B_), dim3(32, 8)>>>(x);
    k_ln<<<B_ * E_, 128>>>(ln_g, ln_b);

    k_qkv<<<dim3(24, 16), 256, DBUF_BYTES>>>(w_q, w_k, w_v);
    k_qr<<<B_ * H_ * E_, 64>>>(rpr);

    k_logits<<<dim3(E_ / 64, E_ / 128, B_ * H_), 256>>>(dist, attn);

    k_av<<<dim3(E_ / 128, B_ * H_, 2), 256, DBUF_BYTES>>>(attn);
    k_fc<<<dim3(8, 16), 256, DBUF_BYTES>>>(w_fc, out);

    k_norm<<<dim3(64, B_), 256>>>(attn);
    k_ape_den<<<dim3(8, B_), 256>>>(dist);
    k_ape_fin<<<8, 256>>>(ape);
}

// round 17
// speedup vs baseline: 2.8570x; 1.0869x over previous
#include <cuda_runtime.h>
#include <cstdint>
#include <math.h>

#define B_  2
#define E_  1024
#define DM_ 512
#define H_  8
#define DK_ 64
#define DV_ 64
#define MAXN 5

// d_out layout: x_out [B,DM,E] | attn [B,H,E,E] | attn_per_edge [B,E]
constexpr long OFF_ATTN = (long)B_ * DM_ * E_;
constexpr long OFF_APE  = OFF_ATTN + (long)B_ * H_ * E_ * E_;

// ---------------- scratch ------------------------------------------------------
__device__ float g_s [B_*E_*DM_];
__device__ float g_qn[B_*E_*DM_];
__device__ float g_q [B_*H_*E_*DK_];
__device__ float g_k [B_*H_*E_*DK_];
__device__ float g_v [B_*H_*E_*DV_];
__device__ float g_qr[B_*H_*E_*8];
__device__ float g_o [B_*E_*H_*DV_];
__device__ float g_rsum[B_*H_*E_];
__device__ float g_num[B_*E_];
__device__ float g_den[B_*E_];

// ---------------- helpers ------------------------------------------------------
__device__ __forceinline__ float tf32r(float x) {
    asm("cvt.rna.tf32.f32 %0, %0;" : "+f"(x));
    return x;
}
__device__ __forceinline__ uint32_t f2u(float x) { return __float_as_uint(x); }
// raw load: mma.tf32 truncates inputs in HW, explicit cvt not required
__device__ __forceinline__ uint32_t ldr(const float* p) { return f2u(*p); }

__device__ __forceinline__ void mma_tf32(float c[4], const uint32_t a[4], const uint32_t b[2]) {
    asm volatile(
        "mma.sync.aligned.m16n8k8.row.col.f32.tf32.tf32.f32 "
        "{%0,%1,%2,%3}, {%4,%5,%6,%7}, {%8,%9}, {%0,%1,%2,%3};"
        : "+f"(c[0]), "+f"(c[1]), "+f"(c[2]), "+f"(c[3])
        : "r"(a[0]), "r"(a[1]), "r"(a[2]), "r"(a[3]), "r"(b[0]), "r"(b[1]));
}

__device__ __forceinline__ void cp16(float* smem_dst, const float* gsrc) {
    uint32_t s = (uint32_t)__cvta_generic_to_shared(smem_dst);
    asm volatile("cp.async.cg.shared.global [%0], [%1], 16;" :: "r"(s), "l"(gsrc));
}
__device__ __forceinline__ void cp_commit() { asm volatile("cp.async.commit_group;"); }
__device__ __forceinline__ void cp_wait1()  { asm volatile("cp.async.wait_group 1;"); }
__device__ __forceinline__ void cp_wait0()  { asm volatile("cp.async.wait_group 0;"); }

constexpr int ASZ = 128 * 36;   // A tile floats (stride 36)
constexpr int WSZ = 32 * 72;    // W tile floats (stride 72)
constexpr int DBUF_BYTES = 2 * (ASZ + WSZ) * 4;        // 55296
constexpr int AV_SMEM    = DBUF_BYTES + 512 * 4;       // + colacc[512]

// ---------------- 0) zero scratch ----------------------------------------------
__global__ void k_zero() {
    long i = (long)blockIdx.x * 256 + threadIdx.x;
    if (i < B_ * E_)        { g_num[i] = 0.f; g_den[i] = 0.f; }
    if (i < B_ * H_ * E_)   g_rsum[i] = 0.f;
    if (i < (long)B_ * E_ * DM_) g_o[i] = 0.f;
}

// ---------------- 1) transpose x[b][d][e] -> s[b][e][d] ------------------------
__global__ void k_transpose(const float* __restrict__ x) {
    __shared__ float tile[32][33];
    int b  = blockIdx.z;
    int e0 = blockIdx.x * 32, d0 = blockIdx.y * 32;
    int tx = threadIdx.x, ty = threadIdx.y;
#pragma unroll
    for (int l = 0; l < 4; l++) {
        int d = d0 + ty + l * 8;
        tile[ty + l * 8][tx] = x[((long)b * DM_ + d) * E_ + e0 + tx];
    }
    __syncthreads();
#pragma unroll
    for (int l = 0; l < 4; l++) {
        int e = e0 + ty + l * 8;
        g_s[((long)b * E_ + e) * DM_ + d0 + tx] = tile[tx][ty + l * 8];
    }
}

// ---------------- 2) LayerNorm -------------------------------------------------
__global__ void k_ln(const float* __restrict__ gamma, const float* __restrict__ beta) {
    int r = blockIdx.x, t = threadIdx.x;           // 128 threads
    const float* sp = g_s + (long)r * DM_;
    float v[4];
#pragma unroll
    for (int k = 0; k < 4; k++) v[k] = sp[t + 128 * k];

    __shared__ float red[128];
    float s = v[0] + v[1] + v[2] + v[3];
    red[t] = s; __syncthreads();
    for (int o = 64; o > 0; o >>= 1) { if (t < o) red[t] += red[t + o]; __syncthreads(); }
    float mean = red[0] * (1.0f / DM_);
    __syncthreads();

    float sq = 0.f;
#pragma unroll
    for (int k = 0; k < 4; k++) { float d = v[k] - mean; sq += d * d; }
    red[t] = sq; __syncthreads();
    for (int o = 64; o > 0; o >>= 1) { if (t < o) red[t] += red[t + o]; __syncthreads(); }
    float var = red[0] * (1.0f / DM_);
    float inv = 1.0f / sqrtf(var + 1e-6f);

#pragma unroll
    for (int k = 0; k < 4; k++) {
        int d = t + 128 * k;
        g_qn[(long)r * DM_ + d] = (v[k] - mean) * inv * gamma[d] + beta[d];
    }
}

// ---------------- 3) fused QKV GEMM, cp.async double-buffered -------------------
__global__ __launch_bounds__(256, 2)
void k_qkv(const float* __restrict__ w_q, const float* __restrict__ w_k,
           const float* __restrict__ w_v) {
    extern __shared__ float sm[];

    int m0 = blockIdx.y * 128;
    int nglob0 = blockIdx.x * 64;
    int sel = nglob0 >> 9;                 // 0=Q,1=K,2=V
    int n0 = nglob0 & 511;
    const float* A = (sel == 0) ? g_qn : g_s;
    const float* W = (sel == 0) ? w_q : (sel == 1) ? w_k : w_v;

    int tid = threadIdx.x;
    int warp = tid >> 5, lane = tid & 31;
    int g = lane >> 2, t = lane & 3;
    int wm = (warp >> 1) * 32, wn = (warp & 1) * 32;

    auto load_stage = [&](int k0, int st) {
        float* a = sm + st * (ASZ + WSZ);
        float* w = a + ASZ;
#pragma unroll
        for (int l = 0; l < 4; l++) {
            int idx = tid + l * 256;
            int m = idx >> 3, k4 = (idx & 7) * 4;
            cp16(&a[m * 36 + k4], &A[(long)(m0 + m) * DM_ + k0 + k4]);
        }
#pragma unroll
        for (int l = 0; l < 2; l++) {
            int idx = tid + l * 256;
            int k = idx >> 4, n4 = (idx & 15) * 4;
            cp16(&w[k * 72 + n4], &W[(long)(k0 + k) * 512 + n0 + n4]);
        }
        cp_commit();
    };

    float c[2][4][4] = {};
    load_stage(0, 0);

    for (int it = 0; it < 16; it++) {
        int cur = it & 1;
        if (it + 1 < 16) { load_stage((it + 1) * 32, cur ^ 1); cp_wait1(); }
        else cp_wait0();
        __syncthreads();

        const float* As = sm + cur * (ASZ + WSZ);
        const float* Ws = As + ASZ;
#pragma unroll
        for (int kk = 0; kk < 32; kk += 8) {
            uint32_t a[2][4], b[4][2];
#pragma unroll
            for (int mi = 0; mi < 2; mi++) {
                int r = wm + mi * 16;
                a[mi][0] = ldr(&As[(r + g) * 36 + kk + t]);
                a[mi][1] = ldr(&As[(r + g + 8) * 36 + kk + t]);
                a[mi][2] = ldr(&As[(r + g) * 36 + kk + t + 4]);
                a[mi][3] = ldr(&As[(r + g + 8) * 36 + kk + t + 4]);
            }
#pragma unroll
            for (int ni = 0; ni < 4; ni++) {
                int cc = wn + ni * 8 + g;
                b[ni][0] = ldr(&Ws[(kk + t) * 72 + cc]);
                b[ni][1] = ldr(&Ws[(kk + t + 4) * 72 + cc]);
            }
#pragma unroll
            for (int mi = 0; mi < 2; mi++)
#pragma unroll
                for (int ni = 0; ni < 4; ni++) mma_tf32(c[mi][ni], a[mi], b[ni]);
        }
        __syncthreads();
    }

    float* dst = (sel == 0) ? g_q : (sel == 1) ? g_k : g_v;
    float scale = (sel == 0) ? 0.125f : 1.0f;
#pragma unroll
    for (int mi = 0; mi < 2; mi++)
#pragma unroll
        for (int ni = 0; ni < 4; ni++)
#pragma unroll
            for (int e = 0; e < 4; e++) {
                int m = m0 + wm + mi * 16 + g + ((e >= 2) ? 8 : 0);
                int n = n0 + wn + ni * 8 + 2 * t + (e & 1);
                int bb = m >> 10, ee = m & 1023;
                int h = n >> 6, d = n & 63;
                dst[(((long)(bb * H_ + h)) * E_ + ee) * 64 + d] = c[mi][ni][e] * scale;
            }
}

// ---------------- 3b) fc GEMM: o @ w_fc + s -> x_out, cp.async ------------------
__global__ __launch_bounds__(256, 2)
void k_fc(const float* __restrict__ W, float* __restrict__ out) {
    extern __shared__ float sm[];
    int m0 = blockIdx.y * 128, n0 = blockIdx.x * 64;
    int tid = threadIdx.x;
    int warp = tid >> 5, lane = tid & 31;
    int g = lane >> 2, t = lane & 3;
    int wm = (warp >> 1) * 32, wn = (warp & 1) * 32;

    auto load_stage = [&](int k0, int st) {
        float* a = sm + st * (ASZ + WSZ);
        float* w = a + ASZ;
#pragma unroll
        for (int l = 0; l < 4; l++) {
            int idx = tid + l * 256;
            int m = idx >> 3, k4 = (idx & 7) * 4;
            cp16(&a[m * 36 + k4], &g_o[(long)(m0 + m) * DM_ + k0 + k4]);
        }
#pragma unroll
        for (int l = 0; l < 2; l++) {
            int idx = tid + l * 256;
            int k = idx >> 4, n4 = (idx & 15) * 4;
            cp16(&w[k * 72 + n4], &W[(long)(k0 + k) * 512 + n0 + n4]);
        }
        cp_commit();
    };

    float c[2][4][4] = {};
    load_stage(0, 0);

    for (int it = 0; it < 16; it++) {
        int cur = it & 1;
        if (it + 1 < 16) { load_stage((it + 1) * 32, cur ^ 1); cp_wait1(); }
        else cp_wait0();
        __syncthreads();

        const float* As = sm + cur * (ASZ + WSZ);
        const float* Ws = As + ASZ;
#pragma unroll
        for (int kk = 0; kk < 32; kk += 8) {
            uint32_t a[2][4], b[4][2];
#pragma unroll
            for (int mi = 0; mi < 2; mi++) {
                int r = wm + mi * 16;
                a[mi][0] = ldr(&As[(r + g) * 36 + kk + t]);
                a[mi][1] = ldr(&As[(r + g + 8) * 36 + kk + t]);
                a[mi][2] = ldr(&As[(r + g) * 36 + kk + t + 4]);
                a[mi][3] = ldr(&As[(r + g + 8) * 36 + kk + t + 4]);
            }
#pragma unroll
            for (int ni = 0; ni < 4; ni++) {
                int cc = wn + ni * 8 + g;
                b[ni][0] = ldr(&Ws[(kk + t) * 72 + cc]);
                b[ni][1] = ldr(&Ws[(kk + t + 4) * 72 + cc]);
            }
#pragma unroll
            for (int mi = 0; mi < 2; mi++)
#pragma unroll
                for (int ni = 0; ni < 4; ni++) mma_tf32(c[mi][ni], a[mi], b[ni]);
        }
        __syncthreads();
    }

#pragma unroll
    for (int mi = 0; mi < 2; mi++)
#pragma unroll
        for (int ni = 0; ni < 4; ni++)
#pragma unroll
            for (int e = 0; e < 4; e++) {
                int m = m0 + wm + mi * 16 + g + ((e >= 2) ? 8 : 0);
                int n = n0 + wn + ni * 8 + 2 * t + (e & 1);
                int bb = m >> 10, ee = m & 1023;
                float val = c[mi][ni][e] + g_s[(long)m * DM_ + n];
                out[((long)bb * DM_ + n) * E_ + ee] = val;
            }
}

// ---------------- 4) qr[row][c] = qs_row . base_rpr[c] -------------------------
__global__ void k_qr(const float* __restrict__ rpr) {
    int row = blockIdx.x;
    int d = threadIdx.x;                       // 64 threads
    int lane = d & 31, w = d >> 5;
    float qv = g_q[(long)row * 64 + d];
    __shared__ float sh[2];
#pragma unroll
    for (int c = 0; c < 6; c++) {
        float p = qv * rpr[c * 64 + d];
#pragma unroll
        for (int o = 16; o; o >>= 1) p += __shfl_down_sync(0xffffffffu, p, o);
        if (lane == 0) sh[w] = p;
        __syncthreads();
        if (d == 0) g_qr[(long)row * 8 + c] = sh[0] + sh[1];
        __syncthreads();
    }
}

// ---------------- 5) unnorm attn = exp(qs@k^T + qr[dist]) masked; row sums -----
__global__ __launch_bounds__(256, 2)
void k_logits(const int* __restrict__ dist, float* __restrict__ attn) {
    __shared__ float Qs[128][36];
    __shared__ float Ks[64][36];
    __shared__ float Qr[128][8];
    int bh = blockIdx.z;
    int b  = bh >> 3;
    int i0 = blockIdx.y * 128, j0 = blockIdx.x * 64;
    int tid = threadIdx.x;                 // 256
    int warp = tid >> 5, lane = tid & 31;
    int g = lane >> 2, t = lane & 3;
    int wm = (warp >> 1) * 32, wn = (warp & 1) * 32;

    const float* qp = g_q + ((long)bh * E_ + i0) * 64;
    const float* kp = g_k + ((long)bh * E_ + j0) * 64;

    {   // Qr: 128 rows x 8 = 256 float4
        int r = tid >> 1, c4 = (tid & 1) * 4;
        float4 v = *(const float4*)&g_qr[((long)bh * E_ + i0 + r) * 8 + c4];
        Qr[r][c4 + 0] = v.x; Qr[r][c4 + 1] = v.y; Qr[r][c4 + 2] = v.z; Qr[r][c4 + 3] = v.w;
    }

    float c[2][4][4] = {};
#pragma unroll
    for (int k0 = 0; k0 < 64; k0 += 32) {
#pragma unroll
        for (int l = 0; l < 4; l++) {           // Q chunk: 128x32
            int idx = tid + l * 256;
            int r = idx >> 3, k4 = (idx & 7) * 4;
            float4 v = *(const float4*)&qp[(long)r * 64 + k0 + k4];
            Qs[r][k4 + 0] = tf32r(v.x); Qs[r][k4 + 1] = tf32r(v.y);
            Qs[r][k4 + 2] = tf32r(v.z); Qs[r][k4 + 3] = tf32r(v.w);
        }
#pragma unroll
        for (int l = 0; l < 2; l++) {           // K chunk: 64x32
            int idx = tid + l * 256;
            int r = idx >> 3, k4 = (idx & 7) * 4;
            float4 v = *(const float4*)&kp[(long)r * 64 + k0 + k4];
            Ks[r][k4 + 0] = tf32r(v.x); Ks[r][k4 + 1] = tf32r(v.y);
            Ks[r][k4 + 2] = tf32r(v.z); Ks[r][k4 + 3] = tf32r(v.w);
        }
        __syncthreads();
#pragma unroll
        for (int kk = 0; kk < 32; kk += 8) {
            uint32_t a[2][4], bfr[4][2];
#pragma unroll
            for (int mi = 0; mi < 2; mi++) {
                int r = wm + mi * 16;
                a[mi][0] = f2u(Qs[r + g][kk + t]);
                a[mi][1] = f2u(Qs[r + g + 8][kk + t]);
                a[mi][2] = f2u(Qs[r + g][kk + t + 4]);
                a[mi][3] = f2u(Qs[r + g + 8][kk + t + 4]);
            }
#pragma unroll
            for (int ni = 0; ni < 4; ni++) {
                int cc = wn + ni * 8 + g;
                bfr[ni][0] = f2u(Ks[cc][kk + t]);
                bfr[ni][1] = f2u(Ks[cc][kk + t + 4]);
            }
#pragma unroll
            for (int mi = 0; mi < 2; mi++)
#pragma unroll
                for (int ni = 0; ni < 4; ni++) mma_tf32(c[mi][ni], a[mi], bfr[ni]);
        }
        __syncthreads();
    }

    float rsum[2][2] = {};
#pragma unroll
    for (int mi = 0; mi < 2; mi++)
#pragma unroll
        for (int ni = 0; ni < 4; ni++)
#pragma unroll
            for (int e = 0; e < 4; e++) {
                int ep = e >> 1;
                int il = wm + mi * 16 + g + ep * 8;
                int jl = wn + ni * 8 + 2 * t + (e & 1);
                int i = i0 + il, j = j0 + jl;
                int cd = dist[((long)b * E_ + i) * E_ + j];
                float v = (cd <= MAXN) ? __expf(c[mi][ni][e] + Qr[il][min(cd, MAXN)]) : 0.f;
                attn[((long)bh * E_ + i) * E_ + j] = v;
                rsum[mi][ep] += v;
            }
#pragma unroll
    for (int mi = 0; mi < 2; mi++)
#pragma unroll
        for (int ep = 0; ep < 2; ep++) {
            float s = rsum[mi][ep];
            s += __shfl_xor_sync(0xffffffffu, s, 1);
            s += __shfl_xor_sync(0xffffffffu, s, 2);
            if (t == 0)
                atomicAdd(&g_rsum[(long)bh * E_ + i0 + wm + mi * 16 + g + ep * 8], s);
        }
}

// ---------------- 6) AV + in-place normalization + ape numerator ----------------
// Reads unnormalized attn tiles, mma with V, then normalizes the same smem tile,
// writes it back to attn, and accumulates ape column sums (replaces k_norm).
__global__ __launch_bounds__(256, 2)
void k_av(float* __restrict__ attn) {
    extern __shared__ float sm[];
    float* colacc = sm + 2 * (ASZ + WSZ);      // 512 floats
    __shared__ float sinv[128];

    int bh = blockIdx.y;
    int b = bh >> 3, h = bh & 7;
    int i0 = blockIdx.x * 128;
    int jbase = blockIdx.z * 512;
    int tid = threadIdx.x;
    int warp = tid >> 5, lane = tid & 31;
    int g = lane >> 2, t = lane & 3;
    int wm = (warp >> 1) * 32, wn = (warp & 1) * 32;

    const float* ap = attn + ((long)bh * E_ + i0) * E_;
    const float* vp = g_v + (long)bh * E_ * 64;

    auto load_stage = [&](int j0, int st) {
        float* P = sm + st * (ASZ + WSZ);
        float* V = P + ASZ;
#pragma unroll
        for (int l = 0; l < 4; l++) {
            int idx = tid + l * 256;
            int r = idx >> 3, j4 = (idx & 7) * 4;
            cp16(&P[r * 36 + j4], &ap[(long)r * E_ + j0 + j4]);
        }
#pragma unroll
        for (int l = 0; l < 2; l++) {
            int idx = tid + l * 256;
            int j = idx >> 4, d4 = (idx & 15) * 4;
            cp16(&V[j * 72 + d4], &vp[(long)(j0 + j) * 64 + d4]);
        }
        cp_commit();
    };

    load_stage(jbase, 0);

    // init sinv + colacc while first TMA-ish load is in flight
    if (tid < 128) sinv[tid] = 1.0f / g_rsum[(long)bh * E_ + i0 + tid];
    for (int idx = tid; idx < 512; idx += 256) colacc[idx] = 0.f;

    float c[2][4][4] = {};

    for (int it = 0; it < 16; it++) {
        int cur = it & 1;
        if (it + 1 < 16) { load_stage(jbase + (it + 1) * 32, cur ^ 1); cp_wait1(); }
        else cp_wait0();
        __syncthreads();

        const float* Ps = sm + cur * (ASZ + WSZ);
        const float* Vs = Ps + ASZ;
#pragma unroll
        for (int kk = 0; kk < 32; kk += 8) {
            uint32_t a[2][4], bfr[4][2];
#pragma unroll
            for (int mi = 0; mi < 2; mi++) {
                int r = wm + mi * 16;
                a[mi][0] = ldr(&Ps[(r + g) * 36 + kk + t]);
                a[mi][1] = ldr(&Ps[(r + g + 8) * 36 + kk + t]);
                a[mi][2] = ldr(&Ps[(r + g) * 36 + kk + t + 4]);
                a[mi][3] = ldr(&Ps[(r + g + 8) * 36 + kk + t + 4]);
            }
#pragma unroll
            for (int ni = 0; ni < 4; ni++) {
                int cc = wn + ni * 8 + g;
                bfr[ni][0] = ldr(&Vs[(kk + t) * 72 + cc]);
                bfr[ni][1] = ldr(&Vs[(kk + t + 4) * 72 + cc]);
            }
#pragma unroll
            for (int mi = 0; mi < 2; mi++)
#pragma unroll
                for (int ni = 0; ni < 4; ni++) mma_tf32(c[mi][ni], a[mi], bfr[ni]);
        }

        // normalize tile in smem -> write back to attn; accumulate ape colsums
        {
            int col = tid & 31, rg = tid >> 5;         // 8 row-groups of 16
            int jglob = jbase + it * 32 + col;
            float part = 0.f;
#pragma unroll
            for (int rr = 0; rr < 16; rr++) {
                int r = rg * 16 + rr;
                float v = Ps[r * 36 + col] * sinv[r];
                attn[((long)bh * E_ + i0 + r) * E_ + jglob] = v;
                part += v;
            }
            atomicAdd(&colacc[it * 32 + col], part);
        }
        __syncthreads();
    }

    // flush ape numerator partials (one add per column)
    for (int idx = tid; idx < 512; idx += 256)
        atomicAdd(&g_num[b * 1024 + jbase + idx], colacc[idx]);

#pragma unroll
    for (int mi = 0; mi < 2; mi++)
#pragma unroll
        for (int ni = 0; ni < 4; ni++)
#pragma unroll
            for (int e = 0; e < 4; e++) {
                int ep = e >> 1;
                int il = wm + mi * 16 + g + ep * 8;
                int d = wn + ni * 8 + 2 * t + (e & 1);
                atomicAdd(&g_o[((long)(b * E_ + i0 + il)) * 512 + h * 64 + d],
                          c[mi][ni][e] * sinv[il]);
            }
}

// ---------------- 8) ape denominator + final ------------------------------------
__global__ void k_ape_den(const int* __restrict__ dist) {
    int b = blockIdx.y;
    int i0 = blockIdx.x * 128;
    int t = threadIdx.x;
    int cnt[4] = {};
    for (int rr = 0; rr < 128; rr++) {
        const int* p = dist + ((long)b * E_ + i0 + rr) * E_;
#pragma unroll
        for (int k = 0; k < 4; k++) cnt[k] += (p[t + 256 * k] <= MAXN) ? 1 : 0;
    }
#pragma unroll
    for (int k = 0; k < 4; k++) atomicAdd(&g_den[b * 1024 + t + 256 * k], (float)cnt[k]);
}

__global__ void k_ape_fin(float* __restrict__ out) {
    int i = blockIdx.x * 256 + threadIdx.x;
    if (i < B_ * E_) out[i] = g_num[i] / g_den[i];
}

// ---------------- launcher -----------------------------------------------------
extern "C" void kernel_launch(void* const* d_in, const int* in_sizes, int n_in,
                              void* d_out, int out_size) {
    const float* x    = (const float*)d_in[0];
    const int*   dist = (const int*)  d_in[1];
    const float* rpr  = (const float*)d_in[2];
    const float* w_q  = (const float*)d_in[3];
    const float* w_k  = (const float*)d_in[4];
    const float* w_v  = (const float*)d_in[5];
    const float* w_fc = (const float*)d_in[6];
    const float* ln_g = (const float*)d_in[7];
    const float* ln_b = (const float*)d_in[8];

    float* out  = (float*)d_out;
    float* attn = out + OFF_ATTN;
    float* ape  = out + OFF_APE;

    cudaFuncSetAttribute(k_qkv, cudaFuncAttributeMaxDynamicSharedMemorySize, DBUF_BYTES);
    cudaFuncSetAttribute(k_fc,  cudaFuncAttributeMaxDynamicSharedMemorySize, DBUF_BYTES);
    cudaFuncSetAttribute(k_av,  cudaFuncAttributeMaxDynamicSharedMemorySize, AV_SMEM);

    k_zero<<<4096, 256>>>();
    k_transpose<<<dim3(E_ / 32, DM_ / 32, B_), dim3(32, 8)>>>(x);
    k_ln<<<B_ * E_, 128>>>(ln_g, ln_b);

    k_qkv<<<dim3(24, 16), 256, DBUF_BYTES>>>(w_q, w_k, w_v);
    k_qr<<<B_ * H_ * E_, 64>>>(rpr);

    k_logits<<<dim3(E_ / 64, E_ / 128, B_ * H_), 256>>>(dist, attn);

    k_av<<<dim3(E_ / 128, B_ * H_, 2), 256, AV_SMEM>>>(attn);
    k_fc<<<dim3(8, 16), 256, DBUF_BYTES>>>(w_fc, out);

    k_ape_den<<<dim3(8, B_), 256>>>(dist);
    k_ape_fin<<<8, 256>>>(ape);
}